// round 13
// baseline (speedup 1.0000x reference)
#include <cuda_runtime.h>
#include <cuda_fp16.h>
#include <math.h>
#include <stdint.h>

#define D_MODEL 1024
#define NUM_HEADS 16
#define HEAD_DIM 64
#define SEQ 1024
#define BATCH 2
#define ROWS (BATCH * SEQ)            // 2048
#define OUT_ELEMS   (ROWS * D_MODEL)  // 2,097,152
#define SREL_ELEMS  (BATCH * NUM_HEADS * SEQ * SEQ)  // 33,554,432
#define L2E 1.4426950408889634f

// ---- helpers ----
__device__ __forceinline__ uint32_t smem_u32(const void* p) {
    uint32_t a;
    asm("{ .reg .u64 t; cvta.to.shared.u64 t, %1; cvt.u32.u64 %0, t; }"
        : "=r"(a) : "l"(p));
    return a;
}
__device__ __forceinline__ void cp16(uint32_t dst, const void* src) {
    asm volatile("cp.async.cg.shared.global [%0], [%1], 16;" :: "r"(dst), "l"(src));
}
__device__ __forceinline__ void cp_commit() {
    asm volatile("cp.async.commit_group;" ::: "memory");
}
__device__ __forceinline__ void cp_wait0() {
    asm volatile("cp.async.wait_group 0;" ::: "memory");
}
__device__ __forceinline__ void cp_wait1() {
    asm volatile("cp.async.wait_group 1;" ::: "memory");
}
__device__ __forceinline__ void ldmat_x4(uint32_t& r0, uint32_t& r1,
                                         uint32_t& r2, uint32_t& r3, uint32_t addr) {
    asm volatile("ldmatrix.sync.aligned.m8n8.x4.shared.b16 {%0,%1,%2,%3}, [%4];"
                 : "=r"(r0), "=r"(r1), "=r"(r2), "=r"(r3) : "r"(addr));
}
__device__ __forceinline__ void ldmat_x4t(uint32_t& r0, uint32_t& r1,
                                          uint32_t& r2, uint32_t& r3, uint32_t addr) {
    asm volatile("ldmatrix.sync.aligned.m8n8.x4.trans.shared.b16 {%0,%1,%2,%3}, [%4];"
                 : "=r"(r0), "=r"(r1), "=r"(r2), "=r"(r3) : "r"(addr));
}
__device__ __forceinline__ void ldmat_x2t(uint32_t& r0, uint32_t& r1, uint32_t addr) {
    asm volatile("ldmatrix.sync.aligned.m8n8.x2.trans.shared.b16 {%0,%1}, [%2];"
                 : "=r"(r0), "=r"(r1) : "r"(addr));
}
__device__ __forceinline__ void mma_f16(float* c, const uint32_t* a,
                                        uint32_t b0, uint32_t b1) {
    asm volatile(
        "mma.sync.aligned.m16n8k16.row.col.f32.f16.f16.f32 "
        "{%0,%1,%2,%3}, {%4,%5,%6,%7}, {%8,%9}, {%0,%1,%2,%3};"
        : "+f"(c[0]), "+f"(c[1]), "+f"(c[2]), "+f"(c[3])
        : "r"(a[0]), "r"(a[1]), "r"(a[2]), "r"(a[3]), "r"(b0), "r"(b1));
}
__device__ __forceinline__ float ex2(float x) {
    float r; asm("ex2.approx.f32 %0,%1;" : "=f"(r) : "f"(x)); return r;
}
__device__ __forceinline__ uint32_t packh2(float x, float y) {
    __half2 h = __floats2half2_rn(x, y);
    return *(uint32_t*)&h;
}
// fp16 2-way split: x = hi + lo (to ~2^-22)
__device__ __forceinline__ void split2h(float x, float y, uint32_t& hi, uint32_t& lo) {
    __half hx = __float2half_rn(x), hy = __float2half_rn(y);
    __half lx = __float2half_rn(x - __half2float(hx));
    __half ly = __float2half_rn(y - __half2float(hy));
    __half2 h; h.x = hx; h.y = hy;
    __half2 l; l.x = lx; l.y = ly;
    hi = *(uint32_t*)&h;
    lo = *(uint32_t*)&l;
}

// -------- persistent scratch (fp16) --------
__device__ __half g_qh[OUT_ELEMS], g_ql[OUT_ELEMS];
__device__ __half g_kh[OUT_ELEMS], g_vh[OUT_ELEMS];
__device__ __half g_Wqh[D_MODEL * D_MODEL], g_Wql[D_MODEL * D_MODEL];
__device__ __half g_Wkh[D_MODEL * D_MODEL];
__device__ __half g_Wvh[D_MODEL * D_MODEL];
__device__ __half g_Woh[D_MODEL * D_MODEL];
__device__ __half g_Qh[OUT_ELEMS], g_Ql[OUT_ELEMS];
__device__ __half g_Kh[OUT_ELEMS];
__device__ __half g_Vh[OUT_ELEMS];
__device__ __half g_Oh[OUT_ELEMS];

// ============================================================
// ALL f32->fp16 converts in ONE launch.
// block ranges (256 quads each):
//   [0,2048)     q  -> split
//   [2048,4096)  k  -> hi
//   [4096,6144)  v  -> hi
//   [6144,7168)  Wq -> split
//   [7168,8192)  Wk -> hi
//   [8192,9216)  Wv -> hi
//   [9216,10240) Wo -> hi
// ============================================================
__global__ __launch_bounds__(256) void cvt_all(
    const float* __restrict__ q, const float* __restrict__ k,
    const float* __restrict__ v, const float* __restrict__ Wq,
    const float* __restrict__ Wk, const float* __restrict__ Wv,
    const float* __restrict__ Wo)
{
    const int bid = blockIdx.x;
    const int t = threadIdx.x;
    const float* src;
    __half *hi, *lo = nullptr;
    int i;
    if (bid < 2048)      { i = bid * 256 + t;          src = q;  hi = g_qh; lo = g_ql; }
    else if (bid < 4096) { i = (bid - 2048) * 256 + t; src = k;  hi = g_kh; }
    else if (bid < 6144) { i = (bid - 4096) * 256 + t; src = v;  hi = g_vh; }
    else if (bid < 7168) { i = (bid - 6144) * 256 + t; src = Wq; hi = g_Wqh; lo = g_Wql; }
    else if (bid < 8192) { i = (bid - 7168) * 256 + t; src = Wk; hi = g_Wkh; }
    else if (bid < 9216) { i = (bid - 8192) * 256 + t; src = Wv; hi = g_Wvh; }
    else                 { i = (bid - 9216) * 256 + t; src = Wo; hi = g_Woh; }

    float4 w = ((const float4*)src)[i];
    if (lo) {
        uint32_t h01, l01, h23, l23;
        split2h(w.x, w.y, h01, l01);
        split2h(w.z, w.w, h23, l23);
        ((uint2*)hi)[i] = make_uint2(h01, h23);
        ((uint2*)lo)[i] = make_uint2(l01, l23);
    } else {
        ((uint2*)hi)[i] = make_uint2(packh2(w.x, w.y), packh2(w.z, w.w));
    }
}

#define AST 72
#define BST 136
#define GB_A_BYTES (128 * AST * 2)      // 18432
#define GB_B_BYTES (64 * BST * 2)       // 17408
#define G3_STAGE (2 * GB_A_BYTES + 2 * GB_B_BYTES)   // 71680
#define G3_SMEM (2 * G3_STAGE)                       // 143360
#define G1_STAGE (GB_A_BYTES + GB_B_BYTES)   // 35840

// ============================================================
// 3-pass split GEMM body (Q projection)
// ============================================================
__device__ __forceinline__ void gemm3_body(
    const __half* __restrict__ Ahg, const __half* __restrict__ Alg,
    const __half* __restrict__ Bhg, const __half* __restrict__ Blg,
    const float* __restrict__ bias,
    __half* __restrict__ Ch, __half* __restrict__ Cl, char* smemc)
{
    const uint32_t sb = smem_u32(smemc);
    const int tid = threadIdx.x;
    const int wid = tid >> 5;
    const int lane = tid & 31;
    const int row0 = blockIdx.y * 128;
    const int col0 = blockIdx.x * 128;
    const int mo = (wid >> 1) * 32;
    const int no = (wid & 1) * 64;

    float acc[2][8][4];
    #pragma unroll
    for (int mi = 0; mi < 2; mi++)
        #pragma unroll
        for (int ni = 0; ni < 8; ni++)
            #pragma unroll
            for (int e = 0; e < 4; e++) acc[mi][ni][e] = 0.f;

    auto load_chunk = [&](int c, int s) {
        uint32_t base = sb + s * G3_STAGE;
        const int k0 = c * 64;
        #pragma unroll
        for (int it = 0; it < 4; it++) {
            int idx = tid + it * 256;
            int r = idx >> 3, sg = idx & 7;
            size_t go = (size_t)(row0 + r) * 1024 + k0 + sg * 8;
            uint32_t so = r * 144 + sg * 16;
            cp16(base + so, Ahg + go);
            cp16(base + GB_A_BYTES + so, Alg + go);
        }
        #pragma unroll
        for (int it = 0; it < 4; it++) {
            int idx = tid + it * 256;
            int r = idx >> 4, sg = idx & 15;
            size_t go = (size_t)(k0 + r) * 1024 + col0 + sg * 8;
            uint32_t so = r * 272 + sg * 16;
            cp16(base + 2 * GB_A_BYTES + so, Bhg + go);
            cp16(base + 2 * GB_A_BYTES + GB_B_BYTES + so, Blg + go);
        }
        cp_commit();
    };

    load_chunk(0, 0);

    for (int c = 0; c < 16; c++) {
        const int s = c & 1;
        if (c + 1 < 16) { load_chunk(c + 1, s ^ 1); cp_wait1(); }
        else cp_wait0();
        __syncthreads();

        const uint32_t sAh = sb + s * G3_STAGE;
        const uint32_t sAl = sAh + GB_A_BYTES;
        const uint32_t sBh = sAh + 2 * GB_A_BYTES;
        const uint32_t sBl = sBh + GB_B_BYTES;

        #pragma unroll
        for (int ks = 0; ks < 4; ks++) {
            uint32_t ah[2][4], al[2][4];
            #pragma unroll
            for (int mi = 0; mi < 2; mi++) {
                uint32_t off = ((mo + mi * 16 + (lane & 15)) * AST
                                + ks * 16 + (lane >> 4) * 8) * 2;
                ldmat_x4(ah[mi][0], ah[mi][1], ah[mi][2], ah[mi][3], sAh + off);
                ldmat_x4(al[mi][0], al[mi][1], al[mi][2], al[mi][3], sAl + off);
            }
            #pragma unroll
            for (int ni = 0; ni < 8; ni++) {
                uint32_t offB = ((ks * 16 + (lane & 15)) * BST + no + ni * 8) * 2;
                uint32_t bh0, bh1, bl0, bl1;
                ldmat_x2t(bh0, bh1, sBh + offB);
                ldmat_x2t(bl0, bl1, sBl + offB);
                #pragma unroll
                for (int mi = 0; mi < 2; mi++) {
                    mma_f16(acc[mi][ni], ah[mi], bh0, bh1);
                    mma_f16(acc[mi][ni], ah[mi], bl0, bl1);
                    mma_f16(acc[mi][ni], al[mi], bh0, bh1);
                }
            }
        }
        __syncthreads();
    }

    const int g = lane >> 2, tg = lane & 3;
    #pragma unroll
    for (int mi = 0; mi < 2; mi++) {
        #pragma unroll
        for (int ni = 0; ni < 8; ni++) {
            int colb = col0 + no + ni * 8 + tg * 2;
            float2 bb = *(const float2*)(bias + colb);
            int r0 = row0 + mo + mi * 16 + g;
            uint32_t h0, l0, h1, l1;
            split2h(acc[mi][ni][0] + bb.x, acc[mi][ni][1] + bb.y, h0, l0);
            split2h(acc[mi][ni][2] + bb.x, acc[mi][ni][3] + bb.y, h1, l1);
            *(uint32_t*)(Ch + (size_t)r0 * 1024 + colb) = h0;
            *(uint32_t*)(Cl + (size_t)r0 * 1024 + colb) = l0;
            *(uint32_t*)(Ch + (size_t)(r0 + 8) * 1024 + colb) = h1;
            *(uint32_t*)(Cl + (size_t)(r0 + 8) * 1024 + colb) = l1;
        }
    }
}

// ============================================================
// 1-pass fp16 GEMM body (K/V/O projections)
// ============================================================
__device__ __forceinline__ void gemm1_body(
    const __half* __restrict__ Ahg, const __half* __restrict__ Bhg,
    const float* __restrict__ bias, float* __restrict__ Cf,
    __half* __restrict__ Ch, char* smemc)
{
    const uint32_t sb = smem_u32(smemc);
    const int tid = threadIdx.x;
    const int wid = tid >> 5;
    const int lane = tid & 31;
    const int row0 = blockIdx.y * 128;
    const int col0 = blockIdx.x * 128;
    const int mo = (wid >> 1) * 32;
    const int no = (wid & 1) * 64;

    float acc[2][8][4];
    #pragma unroll
    for (int mi = 0; mi < 2; mi++)
        #pragma unroll
        for (int ni = 0; ni < 8; ni++)
            #pragma unroll
            for (int e = 0; e < 4; e++) acc[mi][ni][e] = 0.f;

    auto load_chunk = [&](int c, int s) {
        uint32_t base = sb + s * G1_STAGE;
        const int k0 = c * 64;
        #pragma unroll
        for (int it = 0; it < 4; it++) {
            int idx = tid + it * 256;
            int r = idx >> 3, sg = idx & 7;
            cp16(base + r * 144 + sg * 16,
                 Ahg + (size_t)(row0 + r) * 1024 + k0 + sg * 8);
        }
        #pragma unroll
        for (int it = 0; it < 4; it++) {
            int idx = tid + it * 256;
            int r = idx >> 4, sg = idx & 15;
            cp16(base + GB_A_BYTES + r * 272 + sg * 16,
                 Bhg + (size_t)(k0 + r) * 1024 + col0 + sg * 8);
        }
        cp_commit();
    };

    load_chunk(0, 0);

    for (int c = 0; c < 16; c++) {
        const int s = c & 1;
        if (c + 1 < 16) { load_chunk(c + 1, s ^ 1); cp_wait1(); }
        else cp_wait0();
        __syncthreads();

        const uint32_t sAh = sb + s * G1_STAGE;
        const uint32_t sBh = sAh + GB_A_BYTES;

        #pragma unroll
        for (int ks = 0; ks < 4; ks++) {
            uint32_t ah[2][4];
            #pragma unroll
            for (int mi = 0; mi < 2; mi++) {
                uint32_t off = ((mo + mi * 16 + (lane & 15)) * AST
                                + ks * 16 + (lane >> 4) * 8) * 2;
                ldmat_x4(ah[mi][0], ah[mi][1], ah[mi][2], ah[mi][3], sAh + off);
            }
            #pragma unroll
            for (int ni = 0; ni < 8; ni++) {
                uint32_t offB = ((ks * 16 + (lane & 15)) * BST + no + ni * 8) * 2;
                uint32_t bh0, bh1;
                ldmat_x2t(bh0, bh1, sBh + offB);
                #pragma unroll
                for (int mi = 0; mi < 2; mi++)
                    mma_f16(acc[mi][ni], ah[mi], bh0, bh1);
            }
        }
        __syncthreads();
    }

    const int g = lane >> 2, tg = lane & 3;
    #pragma unroll
    for (int mi = 0; mi < 2; mi++) {
        #pragma unroll
        for (int ni = 0; ni < 8; ni++) {
            int colb = col0 + no + ni * 8 + tg * 2;
            float2 bb = *(const float2*)(bias + colb);
            int r0 = row0 + mo + mi * 16 + g;
            float w0x = acc[mi][ni][0] + bb.x, w0y = acc[mi][ni][1] + bb.y;
            float w1x = acc[mi][ni][2] + bb.x, w1y = acc[mi][ni][3] + bb.y;
            if (Cf) {
                *(float2*)(Cf + (size_t)r0 * 1024 + colb) = make_float2(w0x, w0y);
                *(float2*)(Cf + (size_t)(r0 + 8) * 1024 + colb) = make_float2(w1x, w1y);
            } else {
                *(uint32_t*)(Ch + (size_t)r0 * 1024 + colb) = packh2(w0x, w0y);
                *(uint32_t*)(Ch + (size_t)(r0 + 8) * 1024 + colb) = packh2(w1x, w1y);
            }
        }
    }
}

// ---- all three projections in ONE launch: z=0 Q(3-pass), z=1 K, z=2 V ----
__global__ __launch_bounds__(256, 1) void proj_all(
    const float* __restrict__ bq, const float* __restrict__ bk,
    const float* __restrict__ bv)
{
    extern __shared__ char smemc[];
    if (blockIdx.z == 0)
        gemm3_body(g_qh, g_ql, g_Wqh, g_Wql, bq, g_Qh, g_Ql, smemc);
    else if (blockIdx.z == 1)
        gemm1_body(g_kh, g_Wkh, bk, nullptr, g_Kh, smemc);
    else
        gemm1_body(g_vh, g_Wvh, bv, nullptr, g_Vh, smemc);
}

// ---- final out projection ----
__global__ __launch_bounds__(256, 1) void out_gemm(
    const float* __restrict__ bo, float* __restrict__ out)
{
    extern __shared__ char smemc[];
    gemm1_body(g_Oh, g_Woh, bo, out, nullptr, smemc);
}

// ============================================================
// qe via HMMA (3-pass fp16 split), fused S_rel stores.
// ============================================================
#define KST 72
#define QE_SMEM ((2 * 128 * KST + 2 * 64 * KST) * 2)   // 55296 B

__global__ __launch_bounds__(256, 1) void qe_hmma(
    const float* __restrict__ er, float* __restrict__ qe_out,
    float* __restrict__ srel_out)
{
    extern __shared__ __half sh[];
    __half* Qh = sh;
    __half* Ql = Qh + 128 * KST;
    __half* Eh = Ql + 128 * KST;
    __half* El = Eh + 64 * KST;

    int t = blockIdx.x;              // 0..71
    int a = 0;
    while (t >= 2 * a + 2) { t -= 2 * a + 2; a++; }
    const int c = 14 - 2 * a + t;
    const int i0 = a * 128, k0 = c * 64;
    const int bh = blockIdx.y;
    const int b = bh >> 4, h = bh & 15;
    const int tid = threadIdx.x;
    const int wid = tid >> 5;
    const int lane = tid & 31;
    const int g = lane >> 2, tg = lane & 3;
    const int mo = wid * 16;
    const int bS = b * SEQ;

    #pragma unroll
    for (int it = 0; it < 4; it++) {
        int idx = tid + it * 256;
        int r = idx >> 3, sg = idx & 7;
        size_t go = (size_t)(bS + i0 + r) * 1024 + h * 64 + sg * 8;
        *(uint4*)((char*)Qh + r * 144 + sg * 16) = *(const uint4*)(g_Qh + go);
        *(uint4*)((char*)Ql + r * 144 + sg * 16) = *(const uint4*)(g_Ql + go);
    }
    #pragma unroll
    for (int it = 0; it < 4; it++) {
        int idx = tid + it * 256;
        int r = idx >> 4, c4 = (idx & 15) << 2;
        float4 v = *(const float4*)(er + (size_t)(k0 + r) * HEAD_DIM + c4);
        uint32_t h01, l01, h23, l23;
        split2h(v.x, v.y, h01, l01);
        split2h(v.z, v.w, h23, l23);
        *(uint2*)(Eh + r * KST + c4) = make_uint2(h01, h23);
        *(uint2*)(El + r * KST + c4) = make_uint2(l01, l23);
    }
    __syncthreads();

    const uint32_t sQh = smem_u32(Qh), sQl = smem_u32(Ql);
    const uint32_t sEh = smem_u32(Eh), sEl = smem_u32(El);

    uint32_t qh[4][4], ql[4][4];
    #pragma unroll
    for (int kb = 0; kb < 4; kb++) {
        uint32_t off = ((mo + (lane & 15)) * KST + kb * 16 + (lane >> 4) * 8) * 2;
        ldmat_x4(qh[kb][0], qh[kb][1], qh[kb][2], qh[kb][3], sQh + off);
        ldmat_x4(ql[kb][0], ql[kb][1], ql[kb][2], ql[kb][3], sQl + off);
    }

    float sa[8][4];
    #pragma unroll
    for (int n = 0; n < 8; n++)
        #pragma unroll
        for (int e = 0; e < 4; e++) sa[n][e] = 0.f;

    #pragma unroll
    for (int ks = 0; ks < 4; ks++) {
        uint32_t ebh[8][2], ebl[8][2];
        #pragma unroll
        for (int np = 0; np < 4; np++) {
            uint32_t off = ((np * 16 + ((lane >> 4) << 3) + (lane & 7)) * KST
                            + ks * 16 + ((lane >> 3) & 1) * 8) * 2;
            uint32_t t0, t1, t2, t3;
            ldmat_x4(t0, t1, t2, t3, sEh + off);
            ebh[2 * np][0] = t0; ebh[2 * np][1] = t1;
            ebh[2 * np + 1][0] = t2; ebh[2 * np + 1][1] = t3;
            ldmat_x4(t0, t1, t2, t3, sEl + off);
            ebl[2 * np][0] = t0; ebl[2 * np][1] = t1;
            ebl[2 * np + 1][0] = t2; ebl[2 * np + 1][1] = t3;
        }
        #pragma unroll
        for (int n = 0; n < 8; n++) {
            mma_f16(sa[n], qh[ks], ebh[n][0], ebh[n][1]);
            mma_f16(sa[n], qh[ks], ebl[n][0], ebl[n][1]);
            mma_f16(sa[n], ql[ks], ebh[n][0], ebh[n][1]);
        }
    }

    const int r0g = i0 + mo + g;
    const int r1g = r0g + 8;
    float* outp = qe_out + ((size_t)bh << 20);
    float* srq = srel_out + ((size_t)bh << 20);
    #pragma unroll
    for (int n = 0; n < 8; n++) {
        int col = k0 + n * 8 + tg * 2;
        float2 w0, w1;
        bool a0 = (col     >= 1023 - r0g);
        bool a1 = (col + 1 >= 1023 - r0g);
        bool a2 = (col     >= 1023 - r1g);
        bool a3 = (col + 1 >= 1023 - r1g);
        w0.x = a0 ? sa[n][0] : 0.f;
        w0.y = a1 ? sa[n][1] : 0.f;
        w1.x = a2 ? sa[n][2] : 0.f;
        w1.y = a3 ? sa[n][3] : 0.f;
        *(float2*)(outp + ((size_t)r0g << 10) + col) = w0;
        *(float2*)(outp + ((size_t)r1g << 10) + col) = w1;
        if (a0) srq[((size_t)r0g << 10) + col     - 1023 + r0g] = sa[n][0];
        if (a1) srq[((size_t)r0g << 10) + col + 1 - 1023 + r0g] = sa[n][1];
        if (a2) srq[((size_t)r1g << 10) + col     - 1023 + r1g] = sa[n][2];
        if (a3) srq[((size_t)r1g << 10) + col + 1 - 1023 + r1g] = sa[n][3];
    }
}

// ============================================================
// ALL zero-fills in one launch:
//   x in [0,56): qe all-zero tiles; x in [56,72): srel upper triangle
// ============================================================
__global__ __launch_bounds__(256) void zero_all(
    float* __restrict__ qe_out, float* __restrict__ srel)
{
    const int bh = blockIdx.y;
    if (blockIdx.x < 56) {
        int t = blockIdx.x;
        int a = 0;
        while (t >= 14 - 2 * a) { t -= 14 - 2 * a; a++; }
        const int i0 = a * 128, k0 = t * 64;
        float* outp = qe_out + ((size_t)bh << 20);
        const float4 z = make_float4(0.f, 0.f, 0.f, 0.f);
        for (int idx = threadIdx.x; idx < 2048; idx += 256) {
            int r = idx >> 4, k4 = (idx & 15) << 2;
            *(float4*)(outp + ((size_t)(i0 + r) << 10) + k0 + k4) = z;
        }
    } else {
        const int i0 = (blockIdx.x - 56) * 64;
        float* srp = srel + ((size_t)bh << 20);
        const int t = threadIdx.x;
        const float4 z = make_float4(0.f, 0.f, 0.f, 0.f);
        for (int r = 0; r < 64; r++) {
            int i = i0 + r;
            float* row = srp + ((size_t)i << 10);
            int jb = i + 1;
            int ja = (jb + 3) & ~3;
            if (t < ja - jb && jb + t < 1024) row[jb + t] = 0.f;
            int j4 = ja + (t << 2);
            if (j4 < 1024) *(float4*)(row + j4) = z;
        }
    }
}

// ============================================================
// Flash attention via HMMA, 1-pass fp16, cp.async KV pipeline,
// register-prefetched srel tiles.
// ============================================================
#define AT_Q_BYTES (128 * KST * 2)      // 18432
#define AT_KV_BYTES (64 * KST * 2)      // 9216
#define AT_STAGE (2 * AT_KV_BYTES)      // 18432
#define AT_SMEM (AT_Q_BYTES + 2 * AT_STAGE)   // 55296

__global__ __launch_bounds__(256, 1) void attn_hmma(const float* __restrict__ srel)
{
    extern __shared__ char smemc[];
    __half* Qh = (__half*)smemc;
    const uint32_t sb = smem_u32(smemc);
    const uint32_t kvbase = sb + AT_Q_BYTES;

    const int tid = threadIdx.x;
    const int wid = tid >> 5;
    const int lane = tid & 31;
    const int g = lane >> 2, tg = lane & 3;
    const int a = 7 - blockIdx.x;
    const int i0 = a * 128;
    const int bh = blockIdx.y;
    const int b = bh >> 4, h = bh & 15;
    const int mo = wid * 16;
    const int njt = 2 * a + 2;
    const int bS = b * SEQ;

    const float* srp = srel + ((size_t)bh << 20);

    auto loadKV = [&](int t, int s) {
        uint32_t base = kvbase + s * AT_STAGE;
        const int j0 = t * 64;
        #pragma unroll
        for (int it = 0; it < 2; it++) {
            int idx = tid + it * 256;
            int r = idx >> 3, sg = idx & 7;
            size_t go = (size_t)(bS + j0 + r) * 1024 + h * 64 + sg * 8;
            uint32_t so = r * 144 + sg * 16;
            cp16(base + so, g_Kh + go);
            cp16(base + AT_KV_BYTES + so, g_Vh + go);
        }
        cp_commit();
    };

    loadKV(0, 0);

    #pragma unroll
    for (int it = 0; it < 4; it++) {
        int idx = tid + it * 256;
        int r = idx >> 3, sg = idx & 7;
        size_t go = (size_t)(bS + i0 + r) * 1024 + h * 64 + sg * 8;
        *(uint4*)((char*)Qh + r * 144 + sg * 16) = *(const uint4*)(g_Qh + go);
    }
    __syncthreads();

    uint32_t qh[4][4];
    #pragma unroll
    for (int kb = 0; kb < 4; kb++) {
        uint32_t off = ((mo + (lane & 15)) * KST + kb * 16 + (lane >> 4) * 8) * 2;
        ldmat_x4(qh[kb][0], qh[kb][1], qh[kb][2], qh[kb][3], sb + off);
    }

    float O[8][4];
    #pragma unroll
    for (int n = 0; n < 8; n++)
        #pragma unroll
        for (int e = 0; e < 4; e++) O[n][e] = 0.f;
    float m0 = -1e30f, m1 = -1e30f, l0 = 0.f, l1 = 0.f;

    const int r0g = i0 + mo + g;
    const int r1g = r0g + 8;

    for (int t = 0; t < njt; t++) {
        const int s = t & 1;
        const int j0 = t * 64;
        if (t + 1 < njt) { loadKV(t + 1, s ^ 1); cp_wait1(); }
        else cp_wait0();
        __syncthreads();

        if (i0 + mo + 15 >= j0) {
            const uint32_t sKh = kvbase + s * AT_STAGE;
            const uint32_t sVh = sKh + AT_KV_BYTES;

            // prefetch srel tile into registers (completes during S mma)
            float2 re0[8], re1[8];
            #pragma unroll
            for (int n = 0; n < 8; n++) {
                int col = j0 + n * 8 + tg * 2;
                re0[n] = *(const float2*)(srp + ((size_t)r0g << 10) + col);
                re1[n] = *(const float2*)(srp + ((size_t)r1g << 10) + col);
            }

            float sa[8][4];
            #pragma unroll
            for (int n = 0; n < 8; n++)
                #pragma unroll
                for (int e = 0; e < 4; e++) sa[n][e] = 0.f;
            #pragma unroll
            for (int ks = 0; ks < 4; ks++) {
                uint32_t kbh[8][2];
                #pragma unroll
                for (int np = 0; np < 4; np++) {
                    uint32_t off = ((np * 16 + ((lane >> 4) << 3) + (lane & 7)) * KST
                                    + ks * 16 + ((lane >> 3) & 1) * 8) * 2;
                    uint32_t t0, t1, t2, t3;
                    ldmat_x4(t0, t1, t2, t3, sKh + off);
                    kbh[2 * np][0] = t0; kbh[2 * np][1] = t1;
                    kbh[2 * np + 1][0] = t2; kbh[2 * np + 1][1] = t3;
                }
                #pragma unroll
                for (int n = 0; n < 8; n++)
                    mma_f16(sa[n], qh[ks], kbh[n][0], kbh[n][1]);
            }

            float tm0 = -1e30f, tm1 = -1e30f;
            #pragma unroll
            for (int n = 0; n < 8; n++) {
                int col = j0 + n * 8 + tg * 2;
                sa[n][0] = (col     <= r0g) ? sa[n][0] * 0.125f + re0[n].x : -1e30f;
                sa[n][1] = (col + 1 <= r0g) ? sa[n][1] * 0.125f + re0[n].y : -1e30f;
                sa[n][2] = (col     <= r1g) ? sa[n][2] * 0.125f + re1[n].x : -1e30f;
                sa[n][3] = (col + 1 <= r1g) ? sa[n][3] * 0.125f + re1[n].y : -1e30f;
                tm0 = fmaxf(tm0, fmaxf(sa[n][0], sa[n][1]));
                tm1 = fmaxf(tm1, fmaxf(sa[n][2], sa[n][3]));
            }
            tm0 = fmaxf(tm0, __shfl_xor_sync(0xffffffffu, tm0, 1));
            tm0 = fmaxf(tm0, __shfl_xor_sync(0xffffffffu, tm0, 2));
            tm1 = fmaxf(tm1, __shfl_xor_sync(0xffffffffu, tm1, 1));
            tm1 = fmaxf(tm1, __shfl_xor_sync(0xffffffffu, tm1, 2));
            float nm0 = fmaxf(m0, tm0), nm1 = fmaxf(m1, tm1);
            float al0 = ex2((m0 - nm0) * L2E), al1 = ex2((m1 - nm1) * L2E);
            m0 = nm0; m1 = nm1;

            float rs0 = 0.f, rs1 = 0.f;
            #pragma unroll
            for (int n = 0; n < 8; n++) {
                sa[n][0] = ex2((sa[n][0] - nm0) * L2E);
                sa[n][1] = ex2((sa[n][1] - nm0) * L2E);
                sa[n][2] = ex2((sa[n][2] - nm1) * L2E);
                sa[n][3] = ex2((sa[n][3] - nm1) * L2E);
                rs0 += sa[n][0] + sa[n][1];
                rs1 += sa[n][2] + sa[n][3];
            }
            rs0 += __shfl_xor_sync(0xffffffffu, rs0, 1);
            rs0 += __shfl_xor_sync(0xffffffffu, rs0, 2);
            rs1 += __shfl_xor_sync(0xffffffffu, rs1, 1);
            rs1 += __shfl_xor_sync(0xffffffffu, rs1, 2);
            l0 = l0 * al0 + rs0;
            l1 = l1 * al1 + rs1;

            #pragma unroll
            for (int n = 0; n < 8; n++) {
                O[n][0] *= al0; O[n][1] *= al0;
                O[n][2] *= al1; O[n][3] *= al1;
            }

            uint32_t pa[4][4];
            #pragma unroll
            for (int kb = 0; kb < 4; kb++) {
                pa[kb][0] = packh2(sa[2 * kb][0],     sa[2 * kb][1]);
                pa[kb][1] = packh2(sa[2 * kb][2],     sa[2 * kb][3]);
                pa[kb][2] = packh2(sa[2 * kb + 1][0], sa[2 * kb + 1][1]);
                pa[kb][3] = packh2(sa[2 * kb + 1][2], sa[2 * kb + 1][3]);
            }

            #pragma unroll
            for (int kb = 0; kb < 4; kb++) {
                uint32_t vbh[8][2];
                #pragma unroll
                for (int np = 0; np < 4; np++) {
                    uint32_t off = ((kb * 16 + (lane & 15)) * KST
                                    + np * 16 + ((lane >> 4) << 3)) * 2;
                    uint32_t t0, t1, t2, t3;
                    ldmat_x4t(t0, t1, t2, t3, sVh + off);
                    vbh[2 * np][0] = t0; vbh[2 * np][1] = t1;
                    vbh[2 * np + 1][0] = t2; vbh[2 * np + 1][1] = t3;
                }
                #pragma unroll
                for (int n = 0; n < 8; n++)
                    mma_f16(O[n], pa[kb], vbh[n][0], vbh[n][1]);
            }
        }
        __syncthreads();
    }

    float iv0 = 1.f / l0, iv1 = 1.f / l1;
    #pragma unroll
    for (int n = 0; n < 8; n++) {
        int col = n * 8 + tg * 2;
        size_t off0 = (size_t)(bS + r0g) * 1024 + h * 64 + col;
        size_t off1 = off0 + 8 * 1024;
        *(uint32_t*)(g_Oh + off0) = packh2(O[n][0] * iv0, O[n][1] * iv0);
        *(uint32_t*)(g_Oh + off1) = packh2(O[n][2] * iv1, O[n][3] * iv1);
    }
}

// ============================================================
// Launcher
// ============================================================
extern "C" void kernel_launch(void* const* d_in, const int* in_sizes, int n_in,
                              void* d_out, int out_size)
{
    (void)in_sizes; (void)n_in; (void)out_size;
    const float* q  = (const float*)d_in[0];
    const float* k  = (const float*)d_in[1];
    const float* v  = (const float*)d_in[2];
    const float* bq = (const float*)d_in[5];
    const float* Wq = (const float*)d_in[4];
    const float* Wk = (const float*)d_in[6];
    const float* bk = (const float*)d_in[7];
    const float* Wv = (const float*)d_in[8];
    const float* bv = (const float*)d_in[9];
    const float* Wo = (const float*)d_in[10];
    const float* bo = (const float*)d_in[11];
    const float* er = (const float*)d_in[12];

    float* out  = (float*)d_out;             // (B,S,D)
    float* srel = out + OUT_ELEMS;           // (B,H,S,S)
    float* qe   = srel + SREL_ELEMS;         // (B,H,S,S)

    cudaFuncSetAttribute(proj_all,
                         cudaFuncAttributeMaxDynamicSharedMemorySize, G3_SMEM);
    cudaFuncSetAttribute(out_gemm,
                         cudaFuncAttributeMaxDynamicSharedMemorySize, 2 * G1_STAGE);
    cudaFuncSetAttribute(qe_hmma,
                         cudaFuncAttributeMaxDynamicSharedMemorySize, QE_SMEM);
    cudaFuncSetAttribute(attn_hmma,
                         cudaFuncAttributeMaxDynamicSharedMemorySize, AT_SMEM);

    cvt_all<<<10240, 256>>>(q, k, v, Wq, Wk, Wv, Wo);

    proj_all<<<dim3(8, 16, 3), 256, G3_SMEM>>>(bq, bk, bv);

    qe_hmma<<<dim3(72, BATCH * NUM_HEADS), 256, QE_SMEM>>>(er, qe, srel);
    zero_all<<<dim3(72, BATCH * NUM_HEADS), 256>>>(qe, srel);

    attn_hmma<<<dim3(8, BATCH * NUM_HEADS), 256, AT_SMEM>>>(srel);

    out_gemm<<<dim3(8, 16), 256, 2 * G1_STAGE>>>(bo, out);
}

// round 15
// speedup vs baseline: 1.4984x; 1.4984x over previous
#include <cuda_runtime.h>
#include <cuda_fp16.h>
#include <math.h>
#include <stdint.h>

#define D_MODEL 1024
#define NUM_HEADS 16
#define HEAD_DIM 64
#define SEQ 1024
#define BATCH 2
#define ROWS (BATCH * SEQ)            // 2048
#define OUT_ELEMS   (ROWS * D_MODEL)  // 2,097,152
#define SREL_ELEMS  (BATCH * NUM_HEADS * SEQ * SEQ)  // 33,554,432
#define L2E 1.4426950408889634f

// ---- helpers ----
__device__ __forceinline__ uint32_t smem_u32(const void* p) {
    uint32_t a;
    asm("{ .reg .u64 t; cvta.to.shared.u64 t, %1; cvt.u32.u64 %0, t; }"
        : "=r"(a) : "l"(p));
    return a;
}
__device__ __forceinline__ void cp16(uint32_t dst, const void* src) {
    asm volatile("cp.async.cg.shared.global [%0], [%1], 16;" :: "r"(dst), "l"(src));
}
__device__ __forceinline__ void cp_commit() {
    asm volatile("cp.async.commit_group;" ::: "memory");
}
__device__ __forceinline__ void cp_wait0() {
    asm volatile("cp.async.wait_group 0;" ::: "memory");
}
__device__ __forceinline__ void cp_wait1() {
    asm volatile("cp.async.wait_group 1;" ::: "memory");
}
__device__ __forceinline__ void ldmat_x4(uint32_t& r0, uint32_t& r1,
                                         uint32_t& r2, uint32_t& r3, uint32_t addr) {
    asm volatile("ldmatrix.sync.aligned.m8n8.x4.shared.b16 {%0,%1,%2,%3}, [%4];"
                 : "=r"(r0), "=r"(r1), "=r"(r2), "=r"(r3) : "r"(addr));
}
__device__ __forceinline__ void ldmat_x4t(uint32_t& r0, uint32_t& r1,
                                          uint32_t& r2, uint32_t& r3, uint32_t addr) {
    asm volatile("ldmatrix.sync.aligned.m8n8.x4.trans.shared.b16 {%0,%1,%2,%3}, [%4];"
                 : "=r"(r0), "=r"(r1), "=r"(r2), "=r"(r3) : "r"(addr));
}
__device__ __forceinline__ void ldmat_x2t(uint32_t& r0, uint32_t& r1, uint32_t addr) {
    asm volatile("ldmatrix.sync.aligned.m8n8.x2.trans.shared.b16 {%0,%1}, [%2];"
                 : "=r"(r0), "=r"(r1) : "r"(addr));
}
__device__ __forceinline__ void mma_f16(float* c, const uint32_t* a,
                                        uint32_t b0, uint32_t b1) {
    asm volatile(
        "mma.sync.aligned.m16n8k16.row.col.f32.f16.f16.f32 "
        "{%0,%1,%2,%3}, {%4,%5,%6,%7}, {%8,%9}, {%0,%1,%2,%3};"
        : "+f"(c[0]), "+f"(c[1]), "+f"(c[2]), "+f"(c[3])
        : "r"(a[0]), "r"(a[1]), "r"(a[2]), "r"(a[3]), "r"(b0), "r"(b1));
}
__device__ __forceinline__ float ex2(float x) {
    float r; asm("ex2.approx.f32 %0,%1;" : "=f"(r) : "f"(x)); return r;
}
__device__ __forceinline__ uint32_t packh2(float x, float y) {
    __half2 h = __floats2half2_rn(x, y);
    return *(uint32_t*)&h;
}
// fp16 2-way split: x = hi + lo (to ~2^-22)
__device__ __forceinline__ void split2h(float x, float y, uint32_t& hi, uint32_t& lo) {
    __half hx = __float2half_rn(x), hy = __float2half_rn(y);
    __half lx = __float2half_rn(x - __half2float(hx));
    __half ly = __float2half_rn(y - __half2float(hy));
    __half2 h; h.x = hx; h.y = hy;
    __half2 l; l.x = lx; l.y = ly;
    hi = *(uint32_t*)&h;
    lo = *(uint32_t*)&l;
}

// -------- persistent scratch (fp16) --------
__device__ __half g_qh[OUT_ELEMS], g_ql[OUT_ELEMS];
__device__ __half g_kh[OUT_ELEMS], g_vh[OUT_ELEMS];
__device__ __half g_Wqh[D_MODEL * D_MODEL], g_Wql[D_MODEL * D_MODEL];
__device__ __half g_Wkh[D_MODEL * D_MODEL];
__device__ __half g_Wvh[D_MODEL * D_MODEL];
__device__ __half g_Woh[D_MODEL * D_MODEL];
__device__ __half g_Qh[OUT_ELEMS], g_Ql[OUT_ELEMS];
__device__ __half g_Kh[OUT_ELEMS];
__device__ __half g_Vh[OUT_ELEMS];
__device__ __half g_Oh[OUT_ELEMS];

// ============================================================
// ALL f32->fp16 converts in ONE launch.
// ============================================================
__global__ __launch_bounds__(256) void cvt_all(
    const float* __restrict__ q, const float* __restrict__ k,
    const float* __restrict__ v, const float* __restrict__ Wq,
    const float* __restrict__ Wk, const float* __restrict__ Wv,
    const float* __restrict__ Wo)
{
    const int bid = blockIdx.x;
    const int t = threadIdx.x;
    const float* src;
    __half *hi, *lo = nullptr;
    int i;
    if (bid < 2048)      { i = bid * 256 + t;          src = q;  hi = g_qh; lo = g_ql; }
    else if (bid < 4096) { i = (bid - 2048) * 256 + t; src = k;  hi = g_kh; }
    else if (bid < 6144) { i = (bid - 4096) * 256 + t; src = v;  hi = g_vh; }
    else if (bid < 7168) { i = (bid - 6144) * 256 + t; src = Wq; hi = g_Wqh; lo = g_Wql; }
    else if (bid < 8192) { i = (bid - 7168) * 256 + t; src = Wk; hi = g_Wkh; }
    else if (bid < 9216) { i = (bid - 8192) * 256 + t; src = Wv; hi = g_Wvh; }
    else                 { i = (bid - 9216) * 256 + t; src = Wo; hi = g_Woh; }

    float4 w = ((const float4*)src)[i];
    if (lo) {
        uint32_t h01, l01, h23, l23;
        split2h(w.x, w.y, h01, l01);
        split2h(w.z, w.w, h23, l23);
        ((uint2*)hi)[i] = make_uint2(h01, h23);
        ((uint2*)lo)[i] = make_uint2(l01, l23);
    } else {
        ((uint2*)hi)[i] = make_uint2(packh2(w.x, w.y), packh2(w.z, w.w));
    }
}

#define AST 72
#define BST 136
#define GB_A_BYTES (128 * AST * 2)      // 18432
#define GB_B_BYTES (64 * BST * 2)       // 17408
#define G3_STAGE (2 * GB_A_BYTES + 2 * GB_B_BYTES)   // 71680
#define G3_SMEM (2 * G3_STAGE)                       // 143360
#define G1_STAGE (GB_A_BYTES + GB_B_BYTES)   // 35840
#define G1_SMEM (2 * G1_STAGE)               // 71680

// ============================================================
// 3-pass split GEMM body (Q projection)
// ============================================================
__device__ __forceinline__ void gemm3_body(
    const __half* __restrict__ Ahg, const __half* __restrict__ Alg,
    const __half* __restrict__ Bhg, const __half* __restrict__ Blg,
    const float* __restrict__ bias,
    __half* __restrict__ Ch, __half* __restrict__ Cl, char* smemc)
{
    const uint32_t sb = smem_u32(smemc);
    const int tid = threadIdx.x;
    const int wid = tid >> 5;
    const int lane = tid & 31;
    const int row0 = blockIdx.y * 128;
    const int col0 = blockIdx.x * 128;
    const int mo = (wid >> 1) * 32;
    const int no = (wid & 1) * 64;

    float acc[2][8][4];
    #pragma unroll
    for (int mi = 0; mi < 2; mi++)
        #pragma unroll
        for (int ni = 0; ni < 8; ni++)
            #pragma unroll
            for (int e = 0; e < 4; e++) acc[mi][ni][e] = 0.f;

    auto load_chunk = [&](int c, int s) {
        uint32_t base = sb + s * G3_STAGE;
        const int k0 = c * 64;
        #pragma unroll
        for (int it = 0; it < 4; it++) {
            int idx = tid + it * 256;
            int r = idx >> 3, sg = idx & 7;
            size_t go = (size_t)(row0 + r) * 1024 + k0 + sg * 8;
            uint32_t so = r * 144 + sg * 16;
            cp16(base + so, Ahg + go);
            cp16(base + GB_A_BYTES + so, Alg + go);
        }
        #pragma unroll
        for (int it = 0; it < 4; it++) {
            int idx = tid + it * 256;
            int r = idx >> 4, sg = idx & 15;
            size_t go = (size_t)(k0 + r) * 1024 + col0 + sg * 8;
            uint32_t so = r * 272 + sg * 16;
            cp16(base + 2 * GB_A_BYTES + so, Bhg + go);
            cp16(base + 2 * GB_A_BYTES + GB_B_BYTES + so, Blg + go);
        }
        cp_commit();
    };

    load_chunk(0, 0);

    for (int c = 0; c < 16; c++) {
        const int s = c & 1;
        if (c + 1 < 16) { load_chunk(c + 1, s ^ 1); cp_wait1(); }
        else cp_wait0();
        __syncthreads();

        const uint32_t sAh = sb + s * G3_STAGE;
        const uint32_t sAl = sAh + GB_A_BYTES;
        const uint32_t sBh = sAh + 2 * GB_A_BYTES;
        const uint32_t sBl = sBh + GB_B_BYTES;

        #pragma unroll
        for (int ks = 0; ks < 4; ks++) {
            uint32_t ah[2][4], al[2][4];
            #pragma unroll
            for (int mi = 0; mi < 2; mi++) {
                uint32_t off = ((mo + mi * 16 + (lane & 15)) * AST
                                + ks * 16 + (lane >> 4) * 8) * 2;
                ldmat_x4(ah[mi][0], ah[mi][1], ah[mi][2], ah[mi][3], sAh + off);
                ldmat_x4(al[mi][0], al[mi][1], al[mi][2], al[mi][3], sAl + off);
            }
            #pragma unroll
            for (int ni = 0; ni < 8; ni++) {
                uint32_t offB = ((ks * 16 + (lane & 15)) * BST + no + ni * 8) * 2;
                uint32_t bh0, bh1, bl0, bl1;
                ldmat_x2t(bh0, bh1, sBh + offB);
                ldmat_x2t(bl0, bl1, sBl + offB);
                #pragma unroll
                for (int mi = 0; mi < 2; mi++) {
                    mma_f16(acc[mi][ni], ah[mi], bh0, bh1);
                    mma_f16(acc[mi][ni], ah[mi], bl0, bl1);
                    mma_f16(acc[mi][ni], al[mi], bh0, bh1);
                }
            }
        }
        __syncthreads();
    }

    const int g = lane >> 2, tg = lane & 3;
    #pragma unroll
    for (int mi = 0; mi < 2; mi++) {
        #pragma unroll
        for (int ni = 0; ni < 8; ni++) {
            int colb = col0 + no + ni * 8 + tg * 2;
            float2 bb = *(const float2*)(bias + colb);
            int r0 = row0 + mo + mi * 16 + g;
            uint32_t h0, l0, h1, l1;
            split2h(acc[mi][ni][0] + bb.x, acc[mi][ni][1] + bb.y, h0, l0);
            split2h(acc[mi][ni][2] + bb.x, acc[mi][ni][3] + bb.y, h1, l1);
            *(uint32_t*)(Ch + (size_t)r0 * 1024 + colb) = h0;
            *(uint32_t*)(Cl + (size_t)r0 * 1024 + colb) = l0;
            *(uint32_t*)(Ch + (size_t)(r0 + 8) * 1024 + colb) = h1;
            *(uint32_t*)(Cl + (size_t)(r0 + 8) * 1024 + colb) = l1;
        }
    }
}

// ============================================================
// 1-pass fp16 GEMM body (K/V/O projections)
// ============================================================
__device__ __forceinline__ void gemm1_body(
    const __half* __restrict__ Ahg, const __half* __restrict__ Bhg,
    const float* __restrict__ bias, float* __restrict__ Cf,
    __half* __restrict__ Ch, char* smemc)
{
    const uint32_t sb = smem_u32(smemc);
    const int tid = threadIdx.x;
    const int wid = tid >> 5;
    const int lane = tid & 31;
    const int row0 = blockIdx.y * 128;
    const int col0 = blockIdx.x * 128;
    const int mo = (wid >> 1) * 32;
    const int no = (wid & 1) * 64;

    float acc[2][8][4];
    #pragma unroll
    for (int mi = 0; mi < 2; mi++)
        #pragma unroll
        for (int ni = 0; ni < 8; ni++)
            #pragma unroll
            for (int e = 0; e < 4; e++) acc[mi][ni][e] = 0.f;

    auto load_chunk = [&](int c, int s) {
        uint32_t base = sb + s * G1_STAGE;
        const int k0 = c * 64;
        #pragma unroll
        for (int it = 0; it < 4; it++) {
            int idx = tid + it * 256;
            int r = idx >> 3, sg = idx & 7;
            cp16(base + r * 144 + sg * 16,
                 Ahg + (size_t)(row0 + r) * 1024 + k0 + sg * 8);
        }
        #pragma unroll
        for (int it = 0; it < 4; it++) {
            int idx = tid + it * 256;
            int r = idx >> 4, sg = idx & 15;
            cp16(base + GB_A_BYTES + r * 272 + sg * 16,
                 Bhg + (size_t)(k0 + r) * 1024 + col0 + sg * 8);
        }
        cp_commit();
    };

    load_chunk(0, 0);

    for (int c = 0; c < 16; c++) {
        const int s = c & 1;
        if (c + 1 < 16) { load_chunk(c + 1, s ^ 1); cp_wait1(); }
        else cp_wait0();
        __syncthreads();

        const uint32_t sAh = sb + s * G1_STAGE;
        const uint32_t sBh = sAh + GB_A_BYTES;

        #pragma unroll
        for (int ks = 0; ks < 4; ks++) {
            uint32_t ah[2][4];
            #pragma unroll
            for (int mi = 0; mi < 2; mi++) {
                uint32_t off = ((mo + mi * 16 + (lane & 15)) * AST
                                + ks * 16 + (lane >> 4) * 8) * 2;
                ldmat_x4(ah[mi][0], ah[mi][1], ah[mi][2], ah[mi][3], sAh + off);
            }
            #pragma unroll
            for (int ni = 0; ni < 8; ni++) {
                uint32_t offB = ((ks * 16 + (lane & 15)) * BST + no + ni * 8) * 2;
                uint32_t bh0, bh1;
                ldmat_x2t(bh0, bh1, sBh + offB);
                #pragma unroll
                for (int mi = 0; mi < 2; mi++)
                    mma_f16(acc[mi][ni], ah[mi], bh0, bh1);
            }
        }
        __syncthreads();
    }

    const int g = lane >> 2, tg = lane & 3;
    #pragma unroll
    for (int mi = 0; mi < 2; mi++) {
        #pragma unroll
        for (int ni = 0; ni < 8; ni++) {
            int colb = col0 + no + ni * 8 + tg * 2;
            float2 bb = *(const float2*)(bias + colb);
            int r0 = row0 + mo + mi * 16 + g;
            float w0x = acc[mi][ni][0] + bb.x, w0y = acc[mi][ni][1] + bb.y;
            float w1x = acc[mi][ni][2] + bb.x, w1y = acc[mi][ni][3] + bb.y;
            if (Cf) {
                *(float2*)(Cf + (size_t)r0 * 1024 + colb) = make_float2(w0x, w0y);
                *(float2*)(Cf + (size_t)(r0 + 8) * 1024 + colb) = make_float2(w1x, w1y);
            } else {
                *(uint32_t*)(Ch + (size_t)r0 * 1024 + colb) = packh2(w0x, w0y);
                *(uint32_t*)(Ch + (size_t)(r0 + 8) * 1024 + colb) = packh2(w1x, w1y);
            }
        }
    }
}

// ---- Q projection (3-pass, 143KB smem) ----
__global__ __launch_bounds__(256, 1) void q_gemm(const float* __restrict__ bq)
{
    extern __shared__ char smemc[];
    gemm3_body(g_qh, g_ql, g_Wqh, g_Wql, bq, g_Qh, g_Ql, smemc);
}

// ---- K+V projections in one launch (1-pass, 71KB smem) ----
__global__ __launch_bounds__(256, 1) void kv_gemm(
    const float* __restrict__ bk, const float* __restrict__ bv)
{
    extern __shared__ char smemc[];
    if (blockIdx.z == 0)
        gemm1_body(g_kh, g_Wkh, bk, nullptr, g_Kh, smemc);
    else
        gemm1_body(g_vh, g_Wvh, bv, nullptr, g_Vh, smemc);
}

// ---- final out projection ----
__global__ __launch_bounds__(256, 1) void out_gemm(
    const float* __restrict__ bo, float* __restrict__ out)
{
    extern __shared__ char smemc[];
    gemm1_body(g_Oh, g_Woh, bo, out, nullptr, smemc);
}

// ============================================================
// qe via HMMA (3-pass fp16 split), fused S_rel stores.
// ============================================================
#define KST 72
#define QE_SMEM ((2 * 128 * KST + 2 * 64 * KST) * 2)   // 55296 B

__global__ __launch_bounds__(256, 1) void qe_hmma(
    const float* __restrict__ er, float* __restrict__ qe_out,
    float* __restrict__ srel_out)
{
    extern __shared__ __half sh[];
    __half* Qh = sh;
    __half* Ql = Qh + 128 * KST;
    __half* Eh = Ql + 128 * KST;
    __half* El = Eh + 64 * KST;

    int t = blockIdx.x;              // 0..71
    int a = 0;
    while (t >= 2 * a + 2) { t -= 2 * a + 2; a++; }
    const int c = 14 - 2 * a + t;
    const int i0 = a * 128, k0 = c * 64;
    const int bh = blockIdx.y;
    const int b = bh >> 4, h = bh & 15;
    const int tid = threadIdx.x;
    const int wid = tid >> 5;
    const int lane = tid & 31;
    const int g = lane >> 2, tg = lane & 3;
    const int mo = wid * 16;
    const int bS = b * SEQ;

    #pragma unroll
    for (int it = 0; it < 4; it++) {
        int idx = tid + it * 256;
        int r = idx >> 3, sg = idx & 7;
        size_t go = (size_t)(bS + i0 + r) * 1024 + h * 64 + sg * 8;
        *(uint4*)((char*)Qh + r * 144 + sg * 16) = *(const uint4*)(g_Qh + go);
        *(uint4*)((char*)Ql + r * 144 + sg * 16) = *(const uint4*)(g_Ql + go);
    }
    #pragma unroll
    for (int it = 0; it < 4; it++) {
        int idx = tid + it * 256;
        int r = idx >> 4, c4 = (idx & 15) << 2;
        float4 v = *(const float4*)(er + (size_t)(k0 + r) * HEAD_DIM + c4);
        uint32_t h01, l01, h23, l23;
        split2h(v.x, v.y, h01, l01);
        split2h(v.z, v.w, h23, l23);
        *(uint2*)(Eh + r * KST + c4) = make_uint2(h01, h23);
        *(uint2*)(El + r * KST + c4) = make_uint2(l01, l23);
    }
    __syncthreads();

    const uint32_t sQh = smem_u32(Qh), sQl = smem_u32(Ql);
    const uint32_t sEh = smem_u32(Eh), sEl = smem_u32(El);

    uint32_t qh[4][4], ql[4][4];
    #pragma unroll
    for (int kb = 0; kb < 4; kb++) {
        uint32_t off = ((mo + (lane & 15)) * KST + kb * 16 + (lane >> 4) * 8) * 2;
        ldmat_x4(qh[kb][0], qh[kb][1], qh[kb][2], qh[kb][3], sQh + off);
        ldmat_x4(ql[kb][0], ql[kb][1], ql[kb][2], ql[kb][3], sQl + off);
    }

    float sa[8][4];
    #pragma unroll
    for (int n = 0; n < 8; n++)
        #pragma unroll
        for (int e = 0; e < 4; e++) sa[n][e] = 0.f;

    #pragma unroll
    for (int ks = 0; ks < 4; ks++) {
        uint32_t ebh[8][2], ebl[8][2];
        #pragma unroll
        for (int np = 0; np < 4; np++) {
            uint32_t off = ((np * 16 + ((lane >> 4) << 3) + (lane & 7)) * KST
                            + ks * 16 + ((lane >> 3) & 1) * 8) * 2;
            uint32_t t0, t1, t2, t3;
            ldmat_x4(t0, t1, t2, t3, sEh + off);
            ebh[2 * np][0] = t0; ebh[2 * np][1] = t1;
            ebh[2 * np + 1][0] = t2; ebh[2 * np + 1][1] = t3;
            ldmat_x4(t0, t1, t2, t3, sEl + off);
            ebl[2 * np][0] = t0; ebl[2 * np][1] = t1;
            ebl[2 * np + 1][0] = t2; ebl[2 * np + 1][1] = t3;
        }
        #pragma unroll
        for (int n = 0; n < 8; n++) {
            mma_f16(sa[n], qh[ks], ebh[n][0], ebh[n][1]);
            mma_f16(sa[n], qh[ks], ebl[n][0], ebl[n][1]);
            mma_f16(sa[n], ql[ks], ebh[n][0], ebh[n][1]);
        }
    }

    const int r0g = i0 + mo + g;
    const int r1g = r0g + 8;
    float* outp = qe_out + ((size_t)bh << 20);
    float* srq = srel_out + ((size_t)bh << 20);
    #pragma unroll
    for (int n = 0; n < 8; n++) {
        int col = k0 + n * 8 + tg * 2;
        float2 w0, w1;
        bool a0 = (col     >= 1023 - r0g);
        bool a1 = (col + 1 >= 1023 - r0g);
        bool a2 = (col     >= 1023 - r1g);
        bool a3 = (col + 1 >= 1023 - r1g);
        w0.x = a0 ? sa[n][0] : 0.f;
        w0.y = a1 ? sa[n][1] : 0.f;
        w1.x = a2 ? sa[n][2] : 0.f;
        w1.y = a3 ? sa[n][3] : 0.f;
        *(float2*)(outp + ((size_t)r0g << 10) + col) = w0;
        *(float2*)(outp + ((size_t)r1g << 10) + col) = w1;
        if (a0) srq[((size_t)r0g << 10) + col     - 1023 + r0g] = sa[n][0];
        if (a1) srq[((size_t)r0g << 10) + col + 1 - 1023 + r0g] = sa[n][1];
        if (a2) srq[((size_t)r1g << 10) + col     - 1023 + r1g] = sa[n][2];
        if (a3) srq[((size_t)r1g << 10) + col + 1 - 1023 + r1g] = sa[n][3];
    }
}

// ============================================================
// ALL zero-fills in one launch (fully independent of other kernels):
//   x in [0,56): qe all-zero tiles; x in [56,72): srel upper triangle
// ============================================================
__global__ __launch_bounds__(256) void zero_all(
    float* __restrict__ qe_out, float* __restrict__ srel)
{
    const int bh = blockIdx.y;
    if (blockIdx.x < 56) {
        int t = blockIdx.x;
        int a = 0;
        while (t >= 14 - 2 * a) { t -= 14 - 2 * a; a++; }
        const int i0 = a * 128, k0 = t * 64;
        float* outp = qe_out + ((size_t)bh << 20);
        const float4 z = make_float4(0.f, 0.f, 0.f, 0.f);
        for (int idx = threadIdx.x; idx < 2048; idx += 256) {
            int r = idx >> 4, k4 = (idx & 15) << 2;
            *(float4*)(outp + ((size_t)(i0 + r) << 10) + k0 + k4) = z;
        }
    } else {
        const int i0 = (blockIdx.x - 56) * 64;
        float* srp = srel + ((size_t)bh << 20);
        const int t = threadIdx.x;
        const float4 z = make_float4(0.f, 0.f, 0.f, 0.f);
        for (int r = 0; r < 64; r++) {
            int i = i0 + r;
            float* row = srp + ((size_t)i << 10);
            int jb = i + 1;
            int ja = (jb + 3) & ~3;
            if (t < ja - jb && jb + t < 1024) row[jb + t] = 0.f;
            int j4 = ja + (t << 2);
            if (j4 < 1024) *(float4*)(row + j4) = z;
        }
    }
}

// ============================================================
// Flash attention via HMMA, 1-pass fp16, cp.async KV pipeline (R12 exact).
// ============================================================
#define AT_Q_BYTES (128 * KST * 2)      // 18432
#define AT_KV_BYTES (64 * KST * 2)      // 9216
#define AT_STAGE (2 * AT_KV_BYTES)      // 18432
#define AT_SMEM (AT_Q_BYTES + 2 * AT_STAGE)   // 55296

__global__ __launch_bounds__(256, 1) void attn_hmma(const float* __restrict__ srel)
{
    extern __shared__ char smemc[];
    __half* Qh = (__half*)smemc;
    const uint32_t sb = smem_u32(smemc);
    const uint32_t kvbase = sb + AT_Q_BYTES;

    const int tid = threadIdx.x;
    const int wid = tid >> 5;
    const int lane = tid & 31;
    const int g = lane >> 2, tg = lane & 3;
    const int a = 7 - blockIdx.x;
    const int i0 = a * 128;
    const int bh = blockIdx.y;
    const int b = bh >> 4, h = bh & 15;
    const int mo = wid * 16;
    const int njt = 2 * a + 2;
    const int bS = b * SEQ;

    const float* srp = srel + ((size_t)bh << 20);

    auto loadKV = [&](int t, int s) {
        uint32_t base = kvbase + s * AT_STAGE;
        const int j0 = t * 64;
        #pragma unroll
        for (int it = 0; it < 2; it++) {
            int idx = tid + it * 256;
            int r = idx >> 3, sg = idx & 7;
            size_t go = (size_t)(bS + j0 + r) * 1024 + h * 64 + sg * 8;
            uint32_t so = r * 144 + sg * 16;
            cp16(base + so, g_Kh + go);
            cp16(base + AT_KV_BYTES + so, g_Vh + go);
        }
        cp_commit();
    };

    loadKV(0, 0);

    #pragma unroll
    for (int it = 0; it < 4; it++) {
        int idx = tid + it * 256;
        int r = idx >> 3, sg = idx & 7;
        size_t go = (size_t)(bS + i0 + r) * 1024 + h * 64 + sg * 8;
        *(uint4*)((char*)Qh + r * 144 + sg * 16) = *(const uint4*)(g_Qh + go);
    }
    __syncthreads();

    uint32_t qh[4][4];
    #pragma unroll
    for (int kb = 0; kb < 4; kb++) {
        uint32_t off = ((mo + (lane & 15)) * KST + kb * 16 + (lane >> 4) * 8) * 2;
        ldmat_x4(qh[kb][0], qh[kb][1], qh[kb][2], qh[kb][3], sb + off);
    }

    float O[8][4];
    #pragma unroll
    for (int n = 0; n < 8; n++)
        #pragma unroll
        for (int e = 0; e < 4; e++) O[n][e] = 0.f;
    float m0 = -1e30f, m1 = -1e30f, l0 = 0.f, l1 = 0.f;

    const int r0g = i0 + mo + g;
    const int r1g = r0g + 8;

    for (int t = 0; t < njt; t++) {
        const int s = t & 1;
        const int j0 = t * 64;
        if (t + 1 < njt) { loadKV(t + 1, s ^ 1); cp_wait1(); }
        else cp_wait0();
        __syncthreads();

        if (i0 + mo + 15 >= j0) {
            const uint32_t sKh = kvbase + s * AT_STAGE;
            const uint32_t sVh = sKh + AT_KV_BYTES;

            float sa[8][4];
            #pragma unroll
            for (int n = 0; n < 8; n++)
                #pragma unroll
                for (int e = 0; e < 4; e++) sa[n][e] = 0.f;
            #pragma unroll
            for (int ks = 0; ks < 4; ks++) {
                uint32_t kbh[8][2];
                #pragma unroll
                for (int np = 0; np < 4; np++) {
                    uint32_t off = ((np * 16 + ((lane >> 4) << 3) + (lane & 7)) * KST
                                    + ks * 16 + ((lane >> 3) & 1) * 8) * 2;
                    uint32_t t0, t1, t2, t3;
                    ldmat_x4(t0, t1, t2, t3, sKh + off);
                    kbh[2 * np][0] = t0; kbh[2 * np][1] = t1;
                    kbh[2 * np + 1][0] = t2; kbh[2 * np + 1][1] = t3;
                }
                #pragma unroll
                for (int n = 0; n < 8; n++)
                    mma_f16(sa[n], qh[ks], kbh[n][0], kbh[n][1]);
            }

            float tm0 = -1e30f, tm1 = -1e30f;
            #pragma unroll
            for (int n = 0; n < 8; n++) {
                int col = j0 + n * 8 + tg * 2;
                float2 e0 = *(const float2*)(srp + ((size_t)r0g << 10) + col);
                float2 e1 = *(const float2*)(srp + ((size_t)r1g << 10) + col);
                sa[n][0] = (col     <= r0g) ? sa[n][0] * 0.125f + e0.x : -1e30f;
                sa[n][1] = (col + 1 <= r0g) ? sa[n][1] * 0.125f + e0.y : -1e30f;
                sa[n][2] = (col     <= r1g) ? sa[n][2] * 0.125f + e1.x : -1e30f;
                sa[n][3] = (col + 1 <= r1g) ? sa[n][3] * 0.125f + e1.y : -1e30f;
                tm0 = fmaxf(tm0, fmaxf(sa[n][0], sa[n][1]));
                tm1 = fmaxf(tm1, fmaxf(sa[n][2], sa[n][3]));
            }
            tm0 = fmaxf(tm0, __shfl_xor_sync(0xffffffffu, tm0, 1));
            tm0 = fmaxf(tm0, __shfl_xor_sync(0xffffffffu, tm0, 2));
            tm1 = fmaxf(tm1, __shfl_xor_sync(0xffffffffu, tm1, 1));
            tm1 = fmaxf(tm1, __shfl_xor_sync(0xffffffffu, tm1, 2));
            float nm0 = fmaxf(m0, tm0), nm1 = fmaxf(m1, tm1);
            float al0 = ex2((m0 - nm0) * L2E), al1 = ex2((m1 - nm1) * L2E);
            m0 = nm0; m1 = nm1;

            float rs0 = 0.f, rs1 = 0.f;
            #pragma unroll
            for (int n = 0; n < 8; n++) {
                sa[n][0] = ex2((sa[n][0] - nm0) * L2E);
                sa[n][1] = ex2((sa[n][1] - nm0) * L2E);
                sa[n][2] = ex2((sa[n][2] - nm1) * L2E);
                sa[n][3] = ex2((sa[n][3] - nm1) * L2E);
                rs0 += sa[n][0] + sa[n][1];
                rs1 += sa[n][2] + sa[n][3];
            }
            rs0 += __shfl_xor_sync(0xffffffffu, rs0, 1);
            rs0 += __shfl_xor_sync(0xffffffffu, rs0, 2);
            rs1 += __shfl_xor_sync(0xffffffffu, rs1, 1);
            rs1 += __shfl_xor_sync(0xffffffffu, rs1, 2);
            l0 = l0 * al0 + rs0;
            l1 = l1 * al1 + rs1;

            #pragma unroll
            for (int n = 0; n < 8; n++) {
                O[n][0] *= al0; O[n][1] *= al0;
                O[n][2] *= al1; O[n][3] *= al1;
            }

            uint32_t pa[4][4];
            #pragma unroll
            for (int kb = 0; kb < 4; kb++) {
                pa[kb][0] = packh2(sa[2 * kb][0],     sa[2 * kb][1]);
                pa[kb][1] = packh2(sa[2 * kb][2],     sa[2 * kb][3]);
                pa[kb][2] = packh2(sa[2 * kb + 1][0], sa[2 * kb + 1][1]);
                pa[kb][3] = packh2(sa[2 * kb + 1][2], sa[2 * kb + 1][3]);
            }

            #pragma unroll
            for (int kb = 0; kb < 4; kb++) {
                uint32_t vbh[8][2];
                #pragma unroll
                for (int np = 0; np < 4; np++) {
                    uint32_t off = ((kb * 16 + (lane & 15)) * KST
                                    + np * 16 + ((lane >> 4) << 3)) * 2;
                    uint32_t t0, t1, t2, t3;
                    ldmat_x4t(t0, t1, t2, t3, sVh + off);
                    vbh[2 * np][0] = t0; vbh[2 * np][1] = t1;
                    vbh[2 * np + 1][0] = t2; vbh[2 * np + 1][1] = t3;
                }
                #pragma unroll
                for (int n = 0; n < 8; n++)
                    mma_f16(O[n], pa[kb], vbh[n][0], vbh[n][1]);
            }
        }
        __syncthreads();
    }

    float iv0 = 1.f / l0, iv1 = 1.f / l1;
    #pragma unroll
    for (int n = 0; n < 8; n++) {
        int col = n * 8 + tg * 2;
        size_t off0 = (size_t)(bS + r0g) * 1024 + h * 64 + col;
        size_t off1 = off0 + 8 * 1024;
        *(uint32_t*)(g_Oh + off0) = packh2(O[n][0] * iv0, O[n][1] * iv0);
        *(uint32_t*)(g_Oh + off1) = packh2(O[n][2] * iv1, O[n][3] * iv1);
    }
}

// ============================================================
// Launcher — zero_all forked to a side stream (fully independent work).
// ============================================================
extern "C" void kernel_launch(void* const* d_in, const int* in_sizes, int n_in,
                              void* d_out, int out_size)
{
    (void)in_sizes; (void)n_in; (void)out_size;
    const float* q  = (const float*)d_in[0];
    const float* k  = (const float*)d_in[1];
    const float* v  = (const float*)d_in[2];
    const float* Wq = (const float*)d_in[4];
    const float* bq = (const float*)d_in[5];
    const float* Wk = (const float*)d_in[6];
    const float* bk = (const float*)d_in[7];
    const float* Wv = (const float*)d_in[8];
    const float* bv = (const float*)d_in[9];
    const float* Wo = (const float*)d_in[10];
    const float* bo = (const float*)d_in[11];
    const float* er = (const float*)d_in[12];

    float* out  = (float*)d_out;             // (B,S,D)
    float* srel = out + OUT_ELEMS;           // (B,H,S,S)
    float* qe   = srel + SREL_ELEMS;         // (B,H,S,S)

    static cudaStream_t zs = nullptr;
    static cudaEvent_t ef = nullptr, ej = nullptr;
    if (zs == nullptr) {
        cudaStreamCreateWithFlags(&zs, cudaStreamNonBlocking);
        cudaEventCreateWithFlags(&ef, cudaEventDisableTiming);
        cudaEventCreateWithFlags(&ej, cudaEventDisableTiming);
    }

    cudaFuncSetAttribute(q_gemm,
                         cudaFuncAttributeMaxDynamicSharedMemorySize, G3_SMEM);
    cudaFuncSetAttribute(kv_gemm,
                         cudaFuncAttributeMaxDynamicSharedMemorySize, G1_SMEM);
    cudaFuncSetAttribute(out_gemm,
                         cudaFuncAttributeMaxDynamicSharedMemorySize, G1_SMEM);
    cudaFuncSetAttribute(qe_hmma,
                         cudaFuncAttributeMaxDynamicSharedMemorySize, QE_SMEM);
    cudaFuncSetAttribute(attn_hmma,
                         cudaFuncAttributeMaxDynamicSharedMemorySize, AT_SMEM);

    // fork: zero_all runs concurrently with convert + projections
    cudaEventRecord(ef, 0);
    cudaStreamWaitEvent(zs, ef, 0);
    zero_all<<<dim3(72, BATCH * NUM_HEADS), 256, 0, zs>>>(qe, srel);
    cudaEventRecord(ej, zs);

    cvt_all<<<10240, 256>>>(q, k, v, Wq, Wk, Wv, Wo);

    q_gemm<<<dim3(8, 16), 256, G3_SMEM>>>(bq);
    kv_gemm<<<dim3(8, 16, 2), 256, G1_SMEM>>>(bk, bv);

    qe_hmma<<<dim3(72, BATCH * NUM_HEADS), 256, QE_SMEM>>>(er, qe, srel);

    attn_hmma<<<dim3(8, BATCH * NUM_HEADS), 256, AT_SMEM>>>(srel);

    out_gemm<<<dim3(8, 16), 256, G1_SMEM>>>(bo, out);

    // join: graph end depends on zero_all completion
    cudaStreamWaitEvent(0, ej, 0);
}

// round 16
// speedup vs baseline: 1.5057x; 1.0048x over previous
#include <cuda_runtime.h>
#include <cuda_fp16.h>
#include <math.h>
#include <stdint.h>

#define D_MODEL 1024
#define NUM_HEADS 16
#define HEAD_DIM 64
#define SEQ 1024
#define BATCH 2
#define ROWS (BATCH * SEQ)            // 2048
#define OUT_ELEMS   (ROWS * D_MODEL)  // 2,097,152
#define SREL_ELEMS  (BATCH * NUM_HEADS * SEQ * SEQ)  // 33,554,432
#define L2E 1.4426950408889634f

// ---- helpers ----
__device__ __forceinline__ uint32_t smem_u32(const void* p) {
    uint32_t a;
    asm("{ .reg .u64 t; cvta.to.shared.u64 t, %1; cvt.u32.u64 %0, t; }"
        : "=r"(a) : "l"(p));
    return a;
}
__device__ __forceinline__ void cp16(uint32_t dst, const void* src) {
    asm volatile("cp.async.cg.shared.global [%0], [%1], 16;" :: "r"(dst), "l"(src));
}
__device__ __forceinline__ void cp_commit() {
    asm volatile("cp.async.commit_group;" ::: "memory");
}
__device__ __forceinline__ void cp_wait0() {
    asm volatile("cp.async.wait_group 0;" ::: "memory");
}
__device__ __forceinline__ void cp_wait1() {
    asm volatile("cp.async.wait_group 1;" ::: "memory");
}
__device__ __forceinline__ void ldmat_x4(uint32_t& r0, uint32_t& r1,
                                         uint32_t& r2, uint32_t& r3, uint32_t addr) {
    asm volatile("ldmatrix.sync.aligned.m8n8.x4.shared.b16 {%0,%1,%2,%3}, [%4];"
                 : "=r"(r0), "=r"(r1), "=r"(r2), "=r"(r3) : "r"(addr));
}
__device__ __forceinline__ void ldmat_x4t(uint32_t& r0, uint32_t& r1,
                                          uint32_t& r2, uint32_t& r3, uint32_t addr) {
    asm volatile("ldmatrix.sync.aligned.m8n8.x4.trans.shared.b16 {%0,%1,%2,%3}, [%4];"
                 : "=r"(r0), "=r"(r1), "=r"(r2), "=r"(r3) : "r"(addr));
}
__device__ __forceinline__ void ldmat_x2t(uint32_t& r0, uint32_t& r1, uint32_t addr) {
    asm volatile("ldmatrix.sync.aligned.m8n8.x2.trans.shared.b16 {%0,%1}, [%2];"
                 : "=r"(r0), "=r"(r1) : "r"(addr));
}
__device__ __forceinline__ void mma_f16(float* c, const uint32_t* a,
                                        uint32_t b0, uint32_t b1) {
    asm volatile(
        "mma.sync.aligned.m16n8k16.row.col.f32.f16.f16.f32 "
        "{%0,%1,%2,%3}, {%4,%5,%6,%7}, {%8,%9}, {%0,%1,%2,%3};"
        : "+f"(c[0]), "+f"(c[1]), "+f"(c[2]), "+f"(c[3])
        : "r"(a[0]), "r"(a[1]), "r"(a[2]), "r"(a[3]), "r"(b0), "r"(b1));
}
__device__ __forceinline__ float ex2(float x) {
    float r; asm("ex2.approx.f32 %0,%1;" : "=f"(r) : "f"(x)); return r;
}
__device__ __forceinline__ uint32_t packh2(float x, float y) {
    __half2 h = __floats2half2_rn(x, y);
    return *(uint32_t*)&h;
}
// fp16 2-way split: x = hi + lo (to ~2^-22)
__device__ __forceinline__ void split2h(float x, float y, uint32_t& hi, uint32_t& lo) {
    __half hx = __float2half_rn(x), hy = __float2half_rn(y);
    __half lx = __float2half_rn(x - __half2float(hx));
    __half ly = __float2half_rn(y - __half2float(hy));
    __half2 h; h.x = hx; h.y = hy;
    __half2 l; l.x = lx; l.y = ly;
    hi = *(uint32_t*)&h;
    lo = *(uint32_t*)&l;
}

// -------- persistent scratch (fp16) --------
__device__ __half g_qh[OUT_ELEMS], g_ql[OUT_ELEMS];
__device__ __half g_kh[OUT_ELEMS], g_vh[OUT_ELEMS];
__device__ __half g_Wqh[D_MODEL * D_MODEL], g_Wql[D_MODEL * D_MODEL];
__device__ __half g_Wkh[D_MODEL * D_MODEL];
__device__ __half g_Wvh[D_MODEL * D_MODEL];
__device__ __half g_Woh[D_MODEL * D_MODEL];
__device__ __half g_Qh[OUT_ELEMS], g_Ql[OUT_ELEMS];
__device__ __half g_Kh[OUT_ELEMS];
__device__ __half g_Vh[OUT_ELEMS];
__device__ __half g_Oh[OUT_ELEMS];

// ============================================================
// ALL f32->fp16 converts in ONE launch.
// ============================================================
__global__ __launch_bounds__(256) void cvt_all(
    const float* __restrict__ q, const float* __restrict__ k,
    const float* __restrict__ v, const float* __restrict__ Wq,
    const float* __restrict__ Wk, const float* __restrict__ Wv,
    const float* __restrict__ Wo)
{
    const int bid = blockIdx.x;
    const int t = threadIdx.x;
    const float* src;
    __half *hi, *lo = nullptr;
    int i;
    if (bid < 2048)      { i = bid * 256 + t;          src = q;  hi = g_qh; lo = g_ql; }
    else if (bid < 4096) { i = (bid - 2048) * 256 + t; src = k;  hi = g_kh; }
    else if (bid < 6144) { i = (bid - 4096) * 256 + t; src = v;  hi = g_vh; }
    else if (bid < 7168) { i = (bid - 6144) * 256 + t; src = Wq; hi = g_Wqh; lo = g_Wql; }
    else if (bid < 8192) { i = (bid - 7168) * 256 + t; src = Wk; hi = g_Wkh; }
    else if (bid < 9216) { i = (bid - 8192) * 256 + t; src = Wv; hi = g_Wvh; }
    else                 { i = (bid - 9216) * 256 + t; src = Wo; hi = g_Woh; }

    float4 w = ((const float4*)src)[i];
    if (lo) {
        uint32_t h01, l01, h23, l23;
        split2h(w.x, w.y, h01, l01);
        split2h(w.z, w.w, h23, l23);
        ((uint2*)hi)[i] = make_uint2(h01, h23);
        ((uint2*)lo)[i] = make_uint2(l01, l23);
    } else {
        ((uint2*)hi)[i] = make_uint2(packh2(w.x, w.y), packh2(w.z, w.w));
    }
}

#define AST 72
#define BST 136
#define GB_A_BYTES (128 * AST * 2)      // 18432
#define GB_B_BYTES (64 * BST * 2)       // 17408
#define G3_STAGE (2 * GB_A_BYTES + 2 * GB_B_BYTES)   // 71680
#define G3_SMEM (2 * G3_STAGE)                       // 143360
#define G1_STAGE (GB_A_BYTES + GB_B_BYTES)   // 35840
#define G1_SMEM (2 * G1_STAGE)               // 71680

// ============================================================
// 3-pass split GEMM body (Q projection)
// ============================================================
__device__ __forceinline__ void gemm3_body(
    const __half* __restrict__ Ahg, const __half* __restrict__ Alg,
    const __half* __restrict__ Bhg, const __half* __restrict__ Blg,
    const float* __restrict__ bias,
    __half* __restrict__ Ch, __half* __restrict__ Cl, char* smemc)
{
    const uint32_t sb = smem_u32(smemc);
    const int tid = threadIdx.x;
    const int wid = tid >> 5;
    const int lane = tid & 31;
    const int row0 = blockIdx.y * 128;
    const int col0 = blockIdx.x * 128;
    const int mo = (wid >> 1) * 32;
    const int no = (wid & 1) * 64;

    float acc[2][8][4];
    #pragma unroll
    for (int mi = 0; mi < 2; mi++)
        #pragma unroll
        for (int ni = 0; ni < 8; ni++)
            #pragma unroll
            for (int e = 0; e < 4; e++) acc[mi][ni][e] = 0.f;

    auto load_chunk = [&](int c, int s) {
        uint32_t base = sb + s * G3_STAGE;
        const int k0 = c * 64;
        #pragma unroll
        for (int it = 0; it < 4; it++) {
            int idx = tid + it * 256;
            int r = idx >> 3, sg = idx & 7;
            size_t go = (size_t)(row0 + r) * 1024 + k0 + sg * 8;
            uint32_t so = r * 144 + sg * 16;
            cp16(base + so, Ahg + go);
            cp16(base + GB_A_BYTES + so, Alg + go);
        }
        #pragma unroll
        for (int it = 0; it < 4; it++) {
            int idx = tid + it * 256;
            int r = idx >> 4, sg = idx & 15;
            size_t go = (size_t)(k0 + r) * 1024 + col0 + sg * 8;
            uint32_t so = r * 272 + sg * 16;
            cp16(base + 2 * GB_A_BYTES + so, Bhg + go);
            cp16(base + 2 * GB_A_BYTES + GB_B_BYTES + so, Blg + go);
        }
        cp_commit();
    };

    load_chunk(0, 0);

    for (int c = 0; c < 16; c++) {
        const int s = c & 1;
        if (c + 1 < 16) { load_chunk(c + 1, s ^ 1); cp_wait1(); }
        else cp_wait0();
        __syncthreads();

        const uint32_t sAh = sb + s * G3_STAGE;
        const uint32_t sAl = sAh + GB_A_BYTES;
        const uint32_t sBh = sAh + 2 * GB_A_BYTES;
        const uint32_t sBl = sBh + GB_B_BYTES;

        #pragma unroll
        for (int ks = 0; ks < 4; ks++) {
            uint32_t ah[2][4], al[2][4];
            #pragma unroll
            for (int mi = 0; mi < 2; mi++) {
                uint32_t off = ((mo + mi * 16 + (lane & 15)) * AST
                                + ks * 16 + (lane >> 4) * 8) * 2;
                ldmat_x4(ah[mi][0], ah[mi][1], ah[mi][2], ah[mi][3], sAh + off);
                ldmat_x4(al[mi][0], al[mi][1], al[mi][2], al[mi][3], sAl + off);
            }
            #pragma unroll
            for (int ni = 0; ni < 8; ni++) {
                uint32_t offB = ((ks * 16 + (lane & 15)) * BST + no + ni * 8) * 2;
                uint32_t bh0, bh1, bl0, bl1;
                ldmat_x2t(bh0, bh1, sBh + offB);
                ldmat_x2t(bl0, bl1, sBl + offB);
                #pragma unroll
                for (int mi = 0; mi < 2; mi++) {
                    mma_f16(acc[mi][ni], ah[mi], bh0, bh1);
                    mma_f16(acc[mi][ni], ah[mi], bl0, bl1);
                    mma_f16(acc[mi][ni], al[mi], bh0, bh1);
                }
            }
        }
        __syncthreads();
    }

    const int g = lane >> 2, tg = lane & 3;
    #pragma unroll
    for (int mi = 0; mi < 2; mi++) {
        #pragma unroll
        for (int ni = 0; ni < 8; ni++) {
            int colb = col0 + no + ni * 8 + tg * 2;
            float2 bb = *(const float2*)(bias + colb);
            int r0 = row0 + mo + mi * 16 + g;
            uint32_t h0, l0, h1, l1;
            split2h(acc[mi][ni][0] + bb.x, acc[mi][ni][1] + bb.y, h0, l0);
            split2h(acc[mi][ni][2] + bb.x, acc[mi][ni][3] + bb.y, h1, l1);
            *(uint32_t*)(Ch + (size_t)r0 * 1024 + colb) = h0;
            *(uint32_t*)(Cl + (size_t)r0 * 1024 + colb) = l0;
            *(uint32_t*)(Ch + (size_t)(r0 + 8) * 1024 + colb) = h1;
            *(uint32_t*)(Cl + (size_t)(r0 + 8) * 1024 + colb) = l1;
        }
    }
}

// ============================================================
// 1-pass fp16 GEMM body (K/V/O projections)
// ============================================================
__device__ __forceinline__ void gemm1_body(
    const __half* __restrict__ Ahg, const __half* __restrict__ Bhg,
    const float* __restrict__ bias, float* __restrict__ Cf,
    __half* __restrict__ Ch, char* smemc)
{
    const uint32_t sb = smem_u32(smemc);
    const int tid = threadIdx.x;
    const int wid = tid >> 5;
    const int lane = tid & 31;
    const int row0 = blockIdx.y * 128;
    const int col0 = blockIdx.x * 128;
    const int mo = (wid >> 1) * 32;
    const int no = (wid & 1) * 64;

    float acc[2][8][4];
    #pragma unroll
    for (int mi = 0; mi < 2; mi++)
        #pragma unroll
        for (int ni = 0; ni < 8; ni++)
            #pragma unroll
            for (int e = 0; e < 4; e++) acc[mi][ni][e] = 0.f;

    auto load_chunk = [&](int c, int s) {
        uint32_t base = sb + s * G1_STAGE;
        const int k0 = c * 64;
        #pragma unroll
        for (int it = 0; it < 4; it++) {
            int idx = tid + it * 256;
            int r = idx >> 3, sg = idx & 7;
            cp16(base + r * 144 + sg * 16,
                 Ahg + (size_t)(row0 + r) * 1024 + k0 + sg * 8);
        }
        #pragma unroll
        for (int it = 0; it < 4; it++) {
            int idx = tid + it * 256;
            int r = idx >> 4, sg = idx & 15;
            cp16(base + GB_A_BYTES + r * 272 + sg * 16,
                 Bhg + (size_t)(k0 + r) * 1024 + col0 + sg * 8);
        }
        cp_commit();
    };

    load_chunk(0, 0);

    for (int c = 0; c < 16; c++) {
        const int s = c & 1;
        if (c + 1 < 16) { load_chunk(c + 1, s ^ 1); cp_wait1(); }
        else cp_wait0();
        __syncthreads();

        const uint32_t sAh = sb + s * G1_STAGE;
        const uint32_t sBh = sAh + GB_A_BYTES;

        #pragma unroll
        for (int ks = 0; ks < 4; ks++) {
            uint32_t ah[2][4];
            #pragma unroll
            for (int mi = 0; mi < 2; mi++) {
                uint32_t off = ((mo + mi * 16 + (lane & 15)) * AST
                                + ks * 16 + (lane >> 4) * 8) * 2;
                ldmat_x4(ah[mi][0], ah[mi][1], ah[mi][2], ah[mi][3], sAh + off);
            }
            #pragma unroll
            for (int ni = 0; ni < 8; ni++) {
                uint32_t offB = ((ks * 16 + (lane & 15)) * BST + no + ni * 8) * 2;
                uint32_t bh0, bh1;
                ldmat_x2t(bh0, bh1, sBh + offB);
                #pragma unroll
                for (int mi = 0; mi < 2; mi++)
                    mma_f16(acc[mi][ni], ah[mi], bh0, bh1);
            }
        }
        __syncthreads();
    }

    const int g = lane >> 2, tg = lane & 3;
    #pragma unroll
    for (int mi = 0; mi < 2; mi++) {
        #pragma unroll
        for (int ni = 0; ni < 8; ni++) {
            int colb = col0 + no + ni * 8 + tg * 2;
            float2 bb = *(const float2*)(bias + colb);
            int r0 = row0 + mo + mi * 16 + g;
            float w0x = acc[mi][ni][0] + bb.x, w0y = acc[mi][ni][1] + bb.y;
            float w1x = acc[mi][ni][2] + bb.x, w1y = acc[mi][ni][3] + bb.y;
            if (Cf) {
                *(float2*)(Cf + (size_t)r0 * 1024 + colb) = make_float2(w0x, w0y);
                *(float2*)(Cf + (size_t)(r0 + 8) * 1024 + colb) = make_float2(w1x, w1y);
            } else {
                *(uint32_t*)(Ch + (size_t)r0 * 1024 + colb) = packh2(w0x, w0y);
                *(uint32_t*)(Ch + (size_t)(r0 + 8) * 1024 + colb) = packh2(w1x, w1y);
            }
        }
    }
}

// ---- Q projection (3-pass, 143KB smem) ----
__global__ __launch_bounds__(256, 1) void q_gemm(const float* __restrict__ bq)
{
    extern __shared__ char smemc[];
    gemm3_body(g_qh, g_ql, g_Wqh, g_Wql, bq, g_Qh, g_Ql, smemc);
}

// ---- K+V projections in one launch (1-pass, 71KB smem) ----
__global__ __launch_bounds__(256, 1) void kv_gemm(
    const float* __restrict__ bk, const float* __restrict__ bv)
{
    extern __shared__ char smemc[];
    if (blockIdx.z == 0)
        gemm1_body(g_kh, g_Wkh, bk, nullptr, g_Kh, smemc);
    else
        gemm1_body(g_vh, g_Wvh, bv, nullptr, g_Vh, smemc);
}

// ---- final out projection ----
__global__ __launch_bounds__(256, 1) void out_gemm(
    const float* __restrict__ bo, float* __restrict__ out)
{
    extern __shared__ char smemc[];
    gemm1_body(g_Oh, g_Woh, bo, out, nullptr, smemc);
}

// ============================================================
// qe via HMMA (3-pass fp16 split), fused S_rel stores.
// ============================================================
#define KST 72
#define QE_SMEM ((2 * 128 * KST + 2 * 64 * KST) * 2)   // 55296 B

__global__ __launch_bounds__(256, 1) void qe_hmma(
    const float* __restrict__ er, float* __restrict__ qe_out,
    float* __restrict__ srel_out)
{
    extern __shared__ __half sh[];
    __half* Qh = sh;
    __half* Ql = Qh + 128 * KST;
    __half* Eh = Ql + 128 * KST;
    __half* El = Eh + 64 * KST;

    int t = blockIdx.x;              // 0..71
    int a = 0;
    while (t >= 2 * a + 2) { t -= 2 * a + 2; a++; }
    const int c = 14 - 2 * a + t;
    const int i0 = a * 128, k0 = c * 64;
    const int bh = blockIdx.y;
    const int b = bh >> 4, h = bh & 15;
    const int tid = threadIdx.x;
    const int wid = tid >> 5;
    const int lane = tid & 31;
    const int g = lane >> 2, tg = lane & 3;
    const int mo = wid * 16;
    const int bS = b * SEQ;

    #pragma unroll
    for (int it = 0; it < 4; it++) {
        int idx = tid + it * 256;
        int r = idx >> 3, sg = idx & 7;
        size_t go = (size_t)(bS + i0 + r) * 1024 + h * 64 + sg * 8;
        *(uint4*)((char*)Qh + r * 144 + sg * 16) = *(const uint4*)(g_Qh + go);
        *(uint4*)((char*)Ql + r * 144 + sg * 16) = *(const uint4*)(g_Ql + go);
    }
    #pragma unroll
    for (int it = 0; it < 4; it++) {
        int idx = tid + it * 256;
        int r = idx >> 4, c4 = (idx & 15) << 2;
        float4 v = *(const float4*)(er + (size_t)(k0 + r) * HEAD_DIM + c4);
        uint32_t h01, l01, h23, l23;
        split2h(v.x, v.y, h01, l01);
        split2h(v.z, v.w, h23, l23);
        *(uint2*)(Eh + r * KST + c4) = make_uint2(h01, h23);
        *(uint2*)(El + r * KST + c4) = make_uint2(l01, l23);
    }
    __syncthreads();

    const uint32_t sQh = smem_u32(Qh), sQl = smem_u32(Ql);
    const uint32_t sEh = smem_u32(Eh), sEl = smem_u32(El);

    uint32_t qh[4][4], ql[4][4];
    #pragma unroll
    for (int kb = 0; kb < 4; kb++) {
        uint32_t off = ((mo + (lane & 15)) * KST + kb * 16 + (lane >> 4) * 8) * 2;
        ldmat_x4(qh[kb][0], qh[kb][1], qh[kb][2], qh[kb][3], sQh + off);
        ldmat_x4(ql[kb][0], ql[kb][1], ql[kb][2], ql[kb][3], sQl + off);
    }

    float sa[8][4];
    #pragma unroll
    for (int n = 0; n < 8; n++)
        #pragma unroll
        for (int e = 0; e < 4; e++) sa[n][e] = 0.f;

    #pragma unroll
    for (int ks = 0; ks < 4; ks++) {
        uint32_t ebh[8][2], ebl[8][2];
        #pragma unroll
        for (int np = 0; np < 4; np++) {
            uint32_t off = ((np * 16 + ((lane >> 4) << 3) + (lane & 7)) * KST
                            + ks * 16 + ((lane >> 3) & 1) * 8) * 2;
            uint32_t t0, t1, t2, t3;
            ldmat_x4(t0, t1, t2, t3, sEh + off);
            ebh[2 * np][0] = t0; ebh[2 * np][1] = t1;
            ebh[2 * np + 1][0] = t2; ebh[2 * np + 1][1] = t3;
            ldmat_x4(t0, t1, t2, t3, sEl + off);
            ebl[2 * np][0] = t0; ebl[2 * np][1] = t1;
            ebl[2 * np + 1][0] = t2; ebl[2 * np + 1][1] = t3;
        }
        #pragma unroll
        for (int n = 0; n < 8; n++) {
            mma_f16(sa[n], qh[ks], ebh[n][0], ebh[n][1]);
            mma_f16(sa[n], qh[ks], ebl[n][0], ebl[n][1]);
            mma_f16(sa[n], ql[ks], ebh[n][0], ebh[n][1]);
        }
    }

    const int r0g = i0 + mo + g;
    const int r1g = r0g + 8;
    float* outp = qe_out + ((size_t)bh << 20);
    float* srq = srel_out + ((size_t)bh << 20);
    #pragma unroll
    for (int n = 0; n < 8; n++) {
        int col = k0 + n * 8 + tg * 2;
        float2 w0, w1;
        bool a0 = (col     >= 1023 - r0g);
        bool a1 = (col + 1 >= 1023 - r0g);
        bool a2 = (col     >= 1023 - r1g);
        bool a3 = (col + 1 >= 1023 - r1g);
        w0.x = a0 ? sa[n][0] : 0.f;
        w0.y = a1 ? sa[n][1] : 0.f;
        w1.x = a2 ? sa[n][2] : 0.f;
        w1.y = a3 ? sa[n][3] : 0.f;
        *(float2*)(outp + ((size_t)r0g << 10) + col) = w0;
        *(float2*)(outp + ((size_t)r1g << 10) + col) = w1;
        if (a0) srq[((size_t)r0g << 10) + col     - 1023 + r0g] = sa[n][0];
        if (a1) srq[((size_t)r0g << 10) + col + 1 - 1023 + r0g] = sa[n][1];
        if (a2) srq[((size_t)r1g << 10) + col     - 1023 + r1g] = sa[n][2];
        if (a3) srq[((size_t)r1g << 10) + col + 1 - 1023 + r1g] = sa[n][3];
    }
}

// ============================================================
// ALL zero-fills in one launch (fully independent of other kernels):
//   x in [0,56): qe all-zero tiles; x in [56,72): srel upper triangle
// ============================================================
__global__ __launch_bounds__(256) void zero_all(
    float* __restrict__ qe_out, float* __restrict__ srel)
{
    const int bh = blockIdx.y;
    if (blockIdx.x < 56) {
        int t = blockIdx.x;
        int a = 0;
        while (t >= 14 - 2 * a) { t -= 14 - 2 * a; a++; }
        const int i0 = a * 128, k0 = t * 64;
        float* outp = qe_out + ((size_t)bh << 20);
        const float4 z = make_float4(0.f, 0.f, 0.f, 0.f);
        for (int idx = threadIdx.x; idx < 2048; idx += 256) {
            int r = idx >> 4, k4 = (idx & 15) << 2;
            *(float4*)(outp + ((size_t)(i0 + r) << 10) + k0 + k4) = z;
        }
    } else {
        const int i0 = (blockIdx.x - 56) * 64;
        float* srp = srel + ((size_t)bh << 20);
        const int t = threadIdx.x;
        const float4 z = make_float4(0.f, 0.f, 0.f, 0.f);
        for (int r = 0; r < 64; r++) {
            int i = i0 + r;
            float* row = srp + ((size_t)i << 10);
            int jb = i + 1;
            int ja = (jb + 3) & ~3;
            if (t < ja - jb && jb + t < 1024) row[jb + t] = 0.f;
            int j4 = ja + (t << 2);
            if (j4 < 1024) *(float4*)(row + j4) = z;
        }
    }
}

// ============================================================
// Flash attention via HMMA, 1-pass fp16, cp.async KV pipeline.
// ============================================================
#define AT_Q_BYTES (128 * KST * 2)      // 18432
#define AT_KV_BYTES (64 * KST * 2)      // 9216
#define AT_STAGE (2 * AT_KV_BYTES)      // 18432
#define AT_SMEM (AT_Q_BYTES + 2 * AT_STAGE)   // 55296

__global__ __launch_bounds__(256, 1) void attn_hmma(const float* __restrict__ srel)
{
    extern __shared__ char smemc[];
    __half* Qh = (__half*)smemc;
    const uint32_t sb = smem_u32(smemc);
    const uint32_t kvbase = sb + AT_Q_BYTES;

    const int tid = threadIdx.x;
    const int wid = tid >> 5;
    const int lane = tid & 31;
    const int g = lane >> 2, tg = lane & 3;
    const int a = 7 - blockIdx.x;
    const int i0 = a * 128;
    const int bh = blockIdx.y;
    const int b = bh >> 4, h = bh & 15;
    const int mo = wid * 16;
    const int njt = 2 * a + 2;
    const int bS = b * SEQ;

    const float* srp = srel + ((size_t)bh << 20);

    auto loadKV = [&](int t, int s) {
        uint32_t base = kvbase + s * AT_STAGE;
        const int j0 = t * 64;
        #pragma unroll
        for (int it = 0; it < 2; it++) {
            int idx = tid + it * 256;
            int r = idx >> 3, sg = idx & 7;
            size_t go = (size_t)(bS + j0 + r) * 1024 + h * 64 + sg * 8;
            uint32_t so = r * 144 + sg * 16;
            cp16(base + so, g_Kh + go);
            cp16(base + AT_KV_BYTES + so, g_Vh + go);
        }
        cp_commit();
    };

    loadKV(0, 0);

    #pragma unroll
    for (int it = 0; it < 4; it++) {
        int idx = tid + it * 256;
        int r = idx >> 3, sg = idx & 7;
        size_t go = (size_t)(bS + i0 + r) * 1024 + h * 64 + sg * 8;
        *(uint4*)((char*)Qh + r * 144 + sg * 16) = *(const uint4*)(g_Qh + go);
    }
    __syncthreads();

    uint32_t qh[4][4];
    #pragma unroll
    for (int kb = 0; kb < 4; kb++) {
        uint32_t off = ((mo + (lane & 15)) * KST + kb * 16 + (lane >> 4) * 8) * 2;
        ldmat_x4(qh[kb][0], qh[kb][1], qh[kb][2], qh[kb][3], sb + off);
    }

    float O[8][4];
    #pragma unroll
    for (int n = 0; n < 8; n++)
        #pragma unroll
        for (int e = 0; e < 4; e++) O[n][e] = 0.f;
    float m0 = -1e30f, m1 = -1e30f, l0 = 0.f, l1 = 0.f;

    const int r0g = i0 + mo + g;
    const int r1g = r0g + 8;

    for (int t = 0; t < njt; t++) {
        const int s = t & 1;
        const int j0 = t * 64;
        if (t + 1 < njt) { loadKV(t + 1, s ^ 1); cp_wait1(); }
        else cp_wait0();
        __syncthreads();

        if (i0 + mo + 15 >= j0) {
            const uint32_t sKh = kvbase + s * AT_STAGE;
            const uint32_t sVh = sKh + AT_KV_BYTES;

            float sa[8][4];
            #pragma unroll
            for (int n = 0; n < 8; n++)
                #pragma unroll
                for (int e = 0; e < 4; e++) sa[n][e] = 0.f;
            #pragma unroll
            for (int ks = 0; ks < 4; ks++) {
                uint32_t kbh[8][2];
                #pragma unroll
                for (int np = 0; np < 4; np++) {
                    uint32_t off = ((np * 16 + ((lane >> 4) << 3) + (lane & 7)) * KST
                                    + ks * 16 + ((lane >> 3) & 1) * 8) * 2;
                    uint32_t t0, t1, t2, t3;
                    ldmat_x4(t0, t1, t2, t3, sKh + off);
                    kbh[2 * np][0] = t0; kbh[2 * np][1] = t1;
                    kbh[2 * np + 1][0] = t2; kbh[2 * np + 1][1] = t3;
                }
                #pragma unroll
                for (int n = 0; n < 8; n++)
                    mma_f16(sa[n], qh[ks], kbh[n][0], kbh[n][1]);
            }

            float tm0 = -1e30f, tm1 = -1e30f;
            #pragma unroll
            for (int n = 0; n < 8; n++) {
                int col = j0 + n * 8 + tg * 2;
                float2 e0 = *(const float2*)(srp + ((size_t)r0g << 10) + col);
                float2 e1 = *(const float2*)(srp + ((size_t)r1g << 10) + col);
                sa[n][0] = (col     <= r0g) ? sa[n][0] * 0.125f + e0.x : -1e30f;
                sa[n][1] = (col + 1 <= r0g) ? sa[n][1] * 0.125f + e0.y : -1e30f;
                sa[n][2] = (col     <= r1g) ? sa[n][2] * 0.125f + e1.x : -1e30f;
                sa[n][3] = (col + 1 <= r1g) ? sa[n][3] * 0.125f + e1.y : -1e30f;
                tm0 = fmaxf(tm0, fmaxf(sa[n][0], sa[n][1]));
                tm1 = fmaxf(tm1, fmaxf(sa[n][2], sa[n][3]));
            }
            tm0 = fmaxf(tm0, __shfl_xor_sync(0xffffffffu, tm0, 1));
            tm0 = fmaxf(tm0, __shfl_xor_sync(0xffffffffu, tm0, 2));
            tm1 = fmaxf(tm1, __shfl_xor_sync(0xffffffffu, tm1, 1));
            tm1 = fmaxf(tm1, __shfl_xor_sync(0xffffffffu, tm1, 2));
            float nm0 = fmaxf(m0, tm0), nm1 = fmaxf(m1, tm1);
            float al0 = ex2((m0 - nm0) * L2E), al1 = ex2((m1 - nm1) * L2E);
            m0 = nm0; m1 = nm1;

            float rs0 = 0.f, rs1 = 0.f;
            #pragma unroll
            for (int n = 0; n < 8; n++) {
                sa[n][0] = ex2((sa[n][0] - nm0) * L2E);
                sa[n][1] = ex2((sa[n][1] - nm0) * L2E);
                sa[n][2] = ex2((sa[n][2] - nm1) * L2E);
                sa[n][3] = ex2((sa[n][3] - nm1) * L2E);
                rs0 += sa[n][0] + sa[n][1];
                rs1 += sa[n][2] + sa[n][3];
            }
            rs0 += __shfl_xor_sync(0xffffffffu, rs0, 1);
            rs0 += __shfl_xor_sync(0xffffffffu, rs0, 2);
            rs1 += __shfl_xor_sync(0xffffffffu, rs1, 1);
            rs1 += __shfl_xor_sync(0xffffffffu, rs1, 2);
            l0 = l0 * al0 + rs0;
            l1 = l1 * al1 + rs1;

            #pragma unroll
            for (int n = 0; n < 8; n++) {
                O[n][0] *= al0; O[n][1] *= al0;
                O[n][2] *= al1; O[n][3] *= al1;
            }

            uint32_t pa[4][4];
            #pragma unroll
            for (int kb = 0; kb < 4; kb++) {
                pa[kb][0] = packh2(sa[2 * kb][0],     sa[2 * kb][1]);
                pa[kb][1] = packh2(sa[2 * kb][2],     sa[2 * kb][3]);
                pa[kb][2] = packh2(sa[2 * kb + 1][0], sa[2 * kb + 1][1]);
                pa[kb][3] = packh2(sa[2 * kb + 1][2], sa[2 * kb + 1][3]);
            }

            #pragma unroll
            for (int kb = 0; kb < 4; kb++) {
                uint32_t vbh[8][2];
                #pragma unroll
                for (int np = 0; np < 4; np++) {
                    uint32_t off = ((kb * 16 + (lane & 15)) * KST
                                    + np * 16 + ((lane >> 4) << 3)) * 2;
                    uint32_t t0, t1, t2, t3;
                    ldmat_x4t(t0, t1, t2, t3, sVh + off);
                    vbh[2 * np][0] = t0; vbh[2 * np][1] = t1;
                    vbh[2 * np + 1][0] = t2; vbh[2 * np + 1][1] = t3;
                }
                #pragma unroll
                for (int n = 0; n < 8; n++)
                    mma_f16(O[n], pa[kb], vbh[n][0], vbh[n][1]);
            }
        }
        __syncthreads();
    }

    float iv0 = 1.f / l0, iv1 = 1.f / l1;
    #pragma unroll
    for (int n = 0; n < 8; n++) {
        int col = n * 8 + tg * 2;
        size_t off0 = (size_t)(bS + r0g) * 1024 + h * 64 + col;
        size_t off1 = off0 + 8 * 1024;
        *(uint32_t*)(g_Oh + off0) = packh2(O[n][0] * iv0, O[n][1] * iv0);
        *(uint32_t*)(g_Oh + off1) = packh2(O[n][2] * iv1, O[n][3] * iv1);
    }
}

// ============================================================
// Launcher — zero_all AND kv_gemm forked to side streams.
// DAG: cvt → {q_gemm→qe_hmma (main)} ∥ {kv_gemm (ks)} ∥ {zero_all (zs)}
//      attn waits kv; graph end waits zero.
// ============================================================
extern "C" void kernel_launch(void* const* d_in, const int* in_sizes, int n_in,
                              void* d_out, int out_size)
{
    (void)in_sizes; (void)n_in; (void)out_size;
    const float* q  = (const float*)d_in[0];
    const float* k  = (const float*)d_in[1];
    const float* v  = (const float*)d_in[2];
    const float* Wq = (const float*)d_in[4];
    const float* bq = (const float*)d_in[5];
    const float* Wk = (const float*)d_in[6];
    const float* bk = (const float*)d_in[7];
    const float* Wv = (const float*)d_in[8];
    const float* bv = (const float*)d_in[9];
    const float* Wo = (const float*)d_in[10];
    const float* bo = (const float*)d_in[11];
    const float* er = (const float*)d_in[12];

    float* out  = (float*)d_out;             // (B,S,D)
    float* srel = out + OUT_ELEMS;           // (B,H,S,S)
    float* qe   = srel + SREL_ELEMS;         // (B,H,S,S)

    static cudaStream_t zs = nullptr, ks = nullptr;
    static cudaEvent_t ef = nullptr, ej = nullptr, ec = nullptr, ek = nullptr;
    if (zs == nullptr) {
        cudaStreamCreateWithFlags(&zs, cudaStreamNonBlocking);
        cudaStreamCreateWithFlags(&ks, cudaStreamNonBlocking);
        cudaEventCreateWithFlags(&ef, cudaEventDisableTiming);
        cudaEventCreateWithFlags(&ej, cudaEventDisableTiming);
        cudaEventCreateWithFlags(&ec, cudaEventDisableTiming);
        cudaEventCreateWithFlags(&ek, cudaEventDisableTiming);
    }

    cudaFuncSetAttribute(q_gemm,
                         cudaFuncAttributeMaxDynamicSharedMemorySize, G3_SMEM);
    cudaFuncSetAttribute(kv_gemm,
                         cudaFuncAttributeMaxDynamicSharedMemorySize, G1_SMEM);
    cudaFuncSetAttribute(out_gemm,
                         cudaFuncAttributeMaxDynamicSharedMemorySize, G1_SMEM);
    cudaFuncSetAttribute(qe_hmma,
                         cudaFuncAttributeMaxDynamicSharedMemorySize, QE_SMEM);
    cudaFuncSetAttribute(attn_hmma,
                         cudaFuncAttributeMaxDynamicSharedMemorySize, AT_SMEM);

    // fork zero_all (independent of everything; join at end)
    cudaEventRecord(ef, 0);
    cudaStreamWaitEvent(zs, ef, 0);
    zero_all<<<dim3(72, BATCH * NUM_HEADS), 256, 0, zs>>>(qe, srel);
    cudaEventRecord(ej, zs);

    cvt_all<<<10240, 256>>>(q, k, v, Wq, Wk, Wv, Wo);
    cudaEventRecord(ec, 0);

    // fork kv_gemm — runs concurrently with q_gemm + qe_hmma
    cudaStreamWaitEvent(ks, ec, 0);
    kv_gemm<<<dim3(8, 16, 2), 256, G1_SMEM, ks>>>(bk, bv);
    cudaEventRecord(ek, ks);

    q_gemm<<<dim3(8, 16), 256, G3_SMEM>>>(bq);
    qe_hmma<<<dim3(72, BATCH * NUM_HEADS), 256, QE_SMEM>>>(er, qe, srel);

    // attn needs K/V
    cudaStreamWaitEvent(0, ek, 0);
    attn_hmma<<<dim3(8, BATCH * NUM_HEADS), 256, AT_SMEM>>>(srel);

    out_gemm<<<dim3(8, 16), 256, G1_SMEM>>>(bo, out);

    // graph end depends on zero_all
    cudaStreamWaitEvent(0, ej, 0);
}